// round 10
// baseline (speedup 1.0000x reference)
#include <cuda_runtime.h>
#include <stdint.h>

#define BB 2
#define CC 32
#define HH 64
#define WW 64
#define PP 4096
#define FF 288
#define KK 32
#define NBB 32
#define HIDD 64
#define COUTT 64
#define BPB 32                 // kmeans blocks per batch
#define NBLK (BB*BPB)          // 64 total kmeans blocks
#define MAXTILES 256
#define NSLOTS 24

// ---------------- device scratch (static, no allocation) ----------------
__device__ float    g_patches[BB*PP*FF];   // 9.4 MB
__device__ float    g_obs[BB*PP*CC];       // 1.0 MB
__device__ uint32_t g_rank[BB*2*PP];
__device__ int      g_permA[BB*PP];
__device__ int      g_initidx[BB*KK];
__device__ float    g_centers[BB*KK*CC];
__device__ float    g_part[NBLK][KK*CC + KK];   // per-block loop partials
__device__ int      g_cnt[BB*KK];
__device__ int      g_cursor[BB*KK];
__device__ int      g_off[BB*KK + 1];
__device__ int      g_plist[BB*PP];
__device__ int      g_tileBK[MAXTILES];
__device__ int      g_tileM0[MAXTILES];
__device__ int      g_ntiles;
__device__ float    g_attn[BB*KK*NBB];
__device__ float    g_biasv[BB*KK*COUTT];
__device__ float    g_wk[BB*KK*FF*COUTT];  // 4.7 MB
__device__ int      g_bslot[BB][NSLOTS];   // per-batch phase counters
__device__ int      g_gslot[4];            // global phase counters

// ---------------- Threefry-2x32 (JAX-compatible core) ----------------
__host__ __device__ inline void threefry2x32(uint32_t k0, uint32_t k1,
                                             uint32_t x0, uint32_t x1,
                                             uint32_t &o0, uint32_t &o1) {
    uint32_t ks2 = k0 ^ k1 ^ 0x1BD11BDAu;
    uint32_t v0 = x0 + k0, v1 = x1 + k1;
#define TF_R(r) { v0 += v1; v1 = (v1 << (r)) | (v1 >> (32 - (r))); v1 ^= v0; }
    TF_R(13) TF_R(15) TF_R(26) TF_R(6)   v0 += k1;  v1 += ks2 + 1u;
    TF_R(17) TF_R(29) TF_R(16) TF_R(24)  v0 += ks2; v1 += k0  + 2u;
    TF_R(13) TF_R(15) TF_R(26) TF_R(6)   v0 += k0;  v1 += k1  + 3u;
    TF_R(17) TF_R(29) TF_R(16) TF_R(24)  v0 += k1;  v1 += ks2 + 4u;
    TF_R(13) TF_R(15) TF_R(26) TF_R(6)   v0 += ks2; v1 += k0  + 5u;
#undef TF_R
    o0 = v0; o1 = v1;
}

// -------- barrier primitives: release-increment / acquire-poll ------------
__device__ __forceinline__ void bar_arrive(int* slot) {
    __syncthreads();
    if (threadIdx.x == 0) {
        asm volatile("red.release.gpu.global.add.s32 [%0], 1;"
                     :: "l"(slot) : "memory");
    }
}
__device__ __forceinline__ void bar_spin(int* slot, int target) {
    if (threadIdx.x == 0) {
        int v;
        do {
            asm volatile("ld.acquire.gpu.global.s32 %0, [%1];"
                         : "=r"(v) : "l"(slot) : "memory");
        } while (v < target);
    }
    __syncthreads();
}

// ===== fused front: blocks 0..15 = bucket-rank (4-way split per (b,r)),
//       blocks 16..271 = unfold + channel-mean (32 pixels per block) =======
__global__ void __launch_bounds__(1024) k_front(const float* __restrict__ x,
                                                uint4 s0, uint4 s1) {
    __shared__ __align__(16) char smem_u[36928];
    int t = threadIdx.x;
    int bid = blockIdx.x;
    if (bid < 16) {
        // ---------------- rank role ----------------
        unsigned long long* sorted = (unsigned long long*)smem_u;        // 2048 ULL
        int* prefix = (int*)(smem_u + 16384);                            // 1025
        int* cursor = (int*)(smem_u + 20488);                            // 1024
        int* cnt    = (int*)(smem_u + 24584);                            // 1024
        int* wsum   = (int*)(smem_u + 28680);                            // 32
        int br = bid >> 2;               // 0..3 = b*2+r
        int q  = bid & 3;                // quarter of bucket space
        int b = br >> 1, r = br & 1;
        uint4 sk4 = b ? s1 : s0;
        uint32_t kk0 = r ? sk4.z : sk4.x;
        uint32_t kk1 = r ? sk4.w : sk4.y;
        uint32_t kq[4];
#pragma unroll
        for (int qq = 0; qq < 4; qq++) {
            uint32_t o0, o1;
            threefry2x32(kk0, kk1, 0u, (uint32_t)(t + qq*1024), o0, o1);
            kq[qq] = o0 ^ o1;
        }
        cnt[t] = 0;
        __syncthreads();
#pragma unroll
        for (int qq = 0; qq < 4; qq++) atomicAdd(&cnt[kq[qq] >> 22], 1);
        __syncthreads();
        int v = cnt[t];
        int lane = t & 31, wid = t >> 5;
        int s = v;
#pragma unroll
        for (int o = 1; o < 32; o <<= 1) { int u = __shfl_up_sync(0xffffffffu, s, o); if (lane >= o) s += u; }
        if (lane == 31) wsum[wid] = s;
        __syncthreads();
        if (wid == 0) {
            int ws = wsum[lane];
#pragma unroll
            for (int o = 1; o < 32; o <<= 1) { int u = __shfl_up_sync(0xffffffffu, ws, o); if (lane >= o) ws += u; }
            wsum[lane] = ws;
        }
        __syncthreads();
        int incl = s + (wid > 0 ? wsum[wid-1] : 0);
        prefix[t+1] = incl;
        if (t == 0) prefix[0] = 0;
        cursor[t] = incl - v;
        __syncthreads();
        int blo = q << 8, bhi = blo + 256;        // bucket range of this block
        int base = prefix[blo];
#pragma unroll
        for (int qq = 0; qq < 4; qq++) {
            int bkt = kq[qq] >> 22;
            if (bkt >= blo && bkt < bhi) {
                int p = atomicAdd(&cursor[bkt], 1) - base;
                if (p >= 0 && p < 2048)
                    sorted[p] = ((unsigned long long)kq[qq] << 32) | (uint32_t)(t + qq*1024);
            }
        }
        __syncthreads();
#pragma unroll
        for (int qq = 0; qq < 4; qq++) {
            uint32_t key = kq[qq];
            int bkt = key >> 22;
            if (bkt < blo || bkt >= bhi) continue;
            int i = t + qq*1024;
            int lo = prefix[bkt] - base, hi = prefix[bkt+1] - base;
            unsigned long long mine = ((unsigned long long)key << 32) | (uint32_t)i;
            int rr = prefix[bkt];
            for (int j = lo; j < hi; j++) rr += (sorted[j] < mine) ? 1 : 0;
            g_rank[br*PP + i] = (uint32_t)rr;
        }
    } else {
        // ---------------- prep role: 32 pixels per block ----------------
        float* stage = (float*)smem_u;           // 32*288 floats = 36 KB
        int g = bid - 16;                        // 0..255
        int warp = t >> 5, lane = t & 31;
        int gp = g*32 + warp;                    // 0..8191
        int b = gp >> 12, p = gp & 4095;
        int py = p >> 6, px = p & 63;
        const float* xc = x + (size_t)(b*CC + lane) * HH * WW;
        float* prow = stage + warp*FF + lane*9;
        float s = 0.f;
#pragma unroll
        for (int i = 0; i < 3; i++) {
            int yy = py + i - 1;
#pragma unroll
            for (int j = 0; j < 3; j++) {
                int xx = px + j - 1;
                float vv = (yy >= 0 && yy < HH && xx >= 0 && xx < WW) ? xc[yy*WW + xx] : 0.f;
                prow[i*3 + j] = vv;
                s += vv;
            }
        }
        g_obs[(size_t)gp * CC + lane] = s / 9.f;
        __syncthreads();
        size_t base = (size_t)(g*32) * FF;
        for (int i = t; i < 32*FF; i += 1024) g_patches[base + i] = stage[i];
    }
}

// ------- seed: global init + perm scatter + init-center gather (2 blocks) ---
__global__ void k_seed() {
    int b = blockIdx.x, t = threadIdx.x;   // 2 x 1024
    if (t < NSLOTS) g_bslot[b][t] = 0;
    if (b == 0 && t < 4) g_gslot[t] = 0;
    if (t < KK) { g_cnt[b*KK + t] = 0; g_cursor[b*KK + t] = 0; }
#pragma unroll
    for (int q = 0; q < 4; q++) {
        int i = t + q*1024;
        g_permA[b*PP + g_rank[(b*2)*PP + i]] = i;
    }
    __syncthreads();
#pragma unroll
    for (int q = 0; q < 4; q++) {
        int i = t + q*1024;
        uint32_t r1 = g_rank[(b*2+1)*PP + i];
        if (r1 < KK) g_initidx[b*KK + r1] = g_permA[b*PP + i];
    }
    __syncthreads();
    if (t < KK*CC) {
        int k = t >> 5, d = t & 31;
        g_centers[b*KK*CC + t] = g_obs[(size_t)(b*PP + g_initidx[b*KK + k])*CC + d];
    }
}

// --- persistent k-means (one barrier/iter, redundant reduce) + tail --------
__global__ void __launch_bounds__(256, 1) k_kmeans(
    float* idx_out,
    const float* __restrict__ kw1, const float* __restrict__ kb1,
    const float* __restrict__ kw2, const float* __restrict__ kb2,
    const float* __restrict__ kw3, const float* __restrict__ kb3,
    const float* __restrict__ bw1, const float* __restrict__ bb1,
    const float* __restrict__ bw2, const float* __restrict__ bb2,
    const float* __restrict__ bw3, const float* __restrict__ bb3)
{
    int bid = blockIdx.x;
    int b = bid >> 5;             // batch
    int sub = bid & 31;           // block within batch
    int t = threadIdx.x;          // 256
    int half = t & 1;
    int lp = t >> 1;              // local point 0..127
    int pi = sub*128 + lp;
    int lane = t & 31;
    int k0 = half * 16;
    __shared__ __align__(16) float sc[KK*CC];
    __shared__ __align__(16) float ssum[KK*CC];
    __shared__ float scn[KK];
    __shared__ float scnt[KK];
    __shared__ float scnt2[KK];
    __shared__ float sq[KK];
    __shared__ float s_sh;

    // point features in registers (persist across all iterations)
    float s[CC]; float sn = 0.f;
    {
        const float* op = g_obs + (size_t)(b*PP + pi) * CC;
#pragma unroll
        for (int d = 0; d < CC; d++) { s[d] = op[d]; sn += s[d]*s[d]; }
    }
    for (int i = t; i < KK*CC; i += 256) sc[i] = __ldcg(&g_centers[b*KK*CC + i]);
    __syncthreads();

    for (int it = 0; it < 20; it++) {
        for (int i = t; i < KK*CC; i += 256) ssum[i] = 0.f;
        if (t < KK) {
            scnt[t] = 0.f;
            float q = 0.f;
#pragma unroll
            for (int d = 0; d < CC; d++) { float c = sc[t*CC + d]; q += c*c; }
            scn[t] = q;
        }
        __syncthreads();
        // ---- assign: 16 clusters per thread, pair-combined ----
        float best = 3.4028235e38f; int bi = 0;
        for (int k = k0; k < k0 + 16; k++) {
            float dot = 0.f;
#pragma unroll
            for (int d = 0; d < CC; d += 4) {
                float4 c4 = *(const float4*)&sc[k*CC + d];
                dot += s[d]*c4.x; dot += s[d+1]*c4.y;
                dot += s[d+2]*c4.z; dot += s[d+3]*c4.w;
            }
            float d2 = sn - 2.0f*dot + scn[k];
            if (d2 < best) { best = d2; bi = k; }
        }
        {
            float ob = __shfl_xor_sync(0xffffffffu, best, 1);
            int   ok = __shfl_xor_sync(0xffffffffu, bi, 1);
            if (ob < best || (ob == best && ok < bi)) { best = ob; bi = ok; }
        }
        if (!half) atomicAdd(&scnt[bi], 1.f);
        // rotated conflict-free smem accumulation
#pragma unroll
        for (int i = 0; i < 16; i++) {
            int d = k0 + ((i + lp) & 15);
            atomicAdd(&ssum[bi*CC + d], s[d]);
        }
        __syncthreads();
        // ---- flush partial ----
#pragma unroll
        for (int q = 0; q < 4; q++) __stcg(&g_part[bid][t + q*256], ssum[t + q*256]);
        if (t < KK) __stcg(&g_part[bid][KK*CC + t], scnt[t]);
        bar_arrive(&g_bslot[b][it]);
        bar_spin(&g_bslot[b][it], BPB);
        // ---- redundant deterministic reduce (identical in every block) ----
        if (t < KK) {
            float c = 0.f;
#pragma unroll
            for (int j = 0; j < BPB; j++) c += __ldcg(&g_part[b*BPB + j][KK*CC + t]);
            scnt2[t] = c;
        }
        __syncthreads();
#pragma unroll
        for (int q = 0; q < 4; q++) {
            int e = t + q*256;
            float acc = 0.f;
#pragma unroll
            for (int j = 0; j < BPB; j++) acc += __ldcg(&g_part[b*BPB + j][e]);
            float cv = scnt2[e >> 5];
            ssum[e] = (cv > 0.f) ? (acc / fmaxf(cv, 1.f)) : sc[e];   // new centers
        }
        __syncthreads();
        // ---- deterministic shift: 8 threads per cluster, shfl-grouped ----
        {
            int k = t >> 3, db = (t & 7) * 4;
            float dsq = 0.f;
#pragma unroll
            for (int d4 = 0; d4 < 4; d4++) {
                float d = ssum[k*CC + db + d4] - sc[k*CC + db + d4];
                dsq += d*d;
            }
#pragma unroll
            for (int o = 1; o < 8; o <<= 1) dsq += __shfl_xor_sync(0xffffffffu, dsq, o);
            if ((t & 7) == 0) sq[k] = sqrtf(dsq);
        }
        __syncthreads();
#pragma unroll
        for (int q = 0; q < 4; q++) { int e = t + q*256; sc[e] = ssum[e]; }
        if (t < KK) {
            float sv = sq[t];
#pragma unroll
            for (int o = 16; o > 0; o >>= 1) sv += __shfl_xor_sync(0xffffffffu, sv, o);
            if (t == 0) s_sh = sv;
        }
        __syncthreads();
        if ((it + 1) >= 20 || s_sh < 20.48f) break;   // TOL*n = 0.005*4096
    }

    // ---- final assignment with converged centers ----
    if (t < KK) {
        float q = 0.f;
#pragma unroll
        for (int d = 0; d < CC; d++) { float c = sc[t*CC + d]; q += c*c; }
        scn[t] = q;
    }
    __syncthreads();
    float best = 3.4028235e38f; int bi = 0;
    for (int k = k0; k < k0 + 16; k++) {
        float dot = 0.f;
#pragma unroll
        for (int d = 0; d < CC; d += 4) {
            float4 c4 = *(const float4*)&sc[k*CC + d];
            dot += s[d]*c4.x; dot += s[d+1]*c4.y;
            dot += s[d+2]*c4.z; dot += s[d+3]*c4.w;
        }
        float d2 = sn - 2.0f*dot + scn[k];
        if (d2 < best) { best = d2; bi = k; }
    }
    {
        float ob = __shfl_xor_sync(0xffffffffu, best, 1);
        int   ok = __shfl_xor_sync(0xffffffffu, bi, 1);
        if (ob < best || (ob == best && ok < bi)) { best = ob; bi = ok; }
    }
    if (!half) {
        if (idx_out) __stcg(&idx_out[b*PP + pi], (float)bi);
        atomicAdd(&g_cnt[b*KK + bi], 1);
    }
    bar_arrive(&g_gslot[0]);
    bar_spin(&g_gslot[0], NBLK);
    // ---- offsets: every block computes redundantly via smem scan ----
    __shared__ int soff[BB*KK + 1];
    {
        int c = 0, sc_ = 0;
        if (t < BB*KK) {
            c = __ldcg(&g_cnt[t]);
            sc_ = c;
#pragma unroll
            for (int o = 1; o < 32; o <<= 1) {
                int u = __shfl_up_sync(0xffffffffu, sc_, o);
                if (lane >= o) sc_ += u;
            }
        }
        __shared__ int w0tot;
        if (t == 31) w0tot = sc_;
        __syncthreads();
        if (t >= 32 && t < 64) sc_ += w0tot;
        if (t < BB*KK) soff[t + 1] = sc_;
        if (t == 0) soff[0] = 0;
        __syncthreads();
    }
    // block 0 publishes g_off + tile list (needed by k_convg)
    if (bid == 0) {
        if (t <= BB*KK) g_off[t] = soff[t];
        if (t == 0) {
            int nt = 0;
            for (int bk = 0; bk < BB*KK; bk++) {
                int c = soff[bk+1] - soff[bk];
                for (int m = 0; m < c; m += 64) { g_tileBK[nt] = bk; g_tileM0[nt] = m; nt++; }
            }
            g_ntiles = nt;
        }
    }
    // ---- scatter pixel list ----
    if (!half) {
        int bk = b*KK + bi;
        int pos = soff[bk] + atomicAdd(&g_cursor[bk], 1);
        __stcg(&g_plist[pos], b*PP + pi);
    }
    bar_arrive(&g_gslot[1]);
    bar_spin(&g_gslot[1], NBLK);
    // ---- per-cluster centroid + MLPs: one block per bk (all 64 blocks) ----
    {
        int bk = bid;
        __shared__ float cen[FF];
        __shared__ float h1[HIDD];
        __shared__ float h2[HIDD];
        int lo = soff[bk], hi = soff[bk+1];
        float a0 = 0.f, a2 = 0.f;
        for (int m = lo; m < hi; m++) {
            int gp = __ldcg(&g_plist[m]);
            const float* pr = g_patches + (size_t)gp*FF;
            a0 += __ldcg(&pr[t]);
            if (t < 32) a2 += __ldcg(&pr[t+256]);
        }
        float dv = fmaxf((float)(hi - lo), 1.f);
        cen[t] = a0 / dv;
        if (t < 32) cen[t+256] = a2 / dv;
        __syncthreads();
        if (t < HIDD) {
            float a = kb1[t];
            for (int f = 0; f < FF; f++) a += cen[f]*kw1[f*HIDD + t];
            h1[t] = fmaxf(a, 0.f);
        }
        __syncthreads();
        if (t < HIDD) {
            float a = kb2[t];
#pragma unroll
            for (int i = 0; i < HIDD; i++) a += h1[i]*kw2[i*HIDD + t];
            h2[t] = fmaxf(a, 0.f);
        }
        __syncthreads();
        if (t < NBB) {
            float a = kb3[t];
#pragma unroll
            for (int i = 0; i < HIDD; i++) a += h2[i]*kw3[i*NBB + t];
            float m = a;
#pragma unroll
            for (int off = 16; off > 0; off >>= 1) m = fmaxf(m, __shfl_xor_sync(0xffffffffu, m, off));
            float e = expf(a - m);
            float ss = e;
#pragma unroll
            for (int off = 16; off > 0; off >>= 1) ss += __shfl_xor_sync(0xffffffffu, ss, off);
            g_attn[bk*NBB + t] = e / ss;
        }
        __syncthreads();
        if (t < HIDD) {
            float a = bb1[t];
            for (int f = 0; f < FF; f++) a += cen[f]*bw1[f*HIDD + t];
            h1[t] = fmaxf(a, 0.f);
        }
        __syncthreads();
        if (t < HIDD) {
            float a = bb2[t];
#pragma unroll
            for (int i = 0; i < HIDD; i++) a += h1[i]*bw2[i*HIDD + t];
            h2[t] = fmaxf(a, 0.f);
        }
        __syncthreads();
        if (t < COUTT) {
            float a = bb3[t];
#pragma unroll
            for (int i = 0; i < HIDD; i++) a += h2[i]*bw3[i*COUTT + t];
            g_biasv[bk*COUTT + t] = a;
        }
    }
}

// ---------------- kernels = attn @ base_kernels ----------------
__global__ void k_wk(const float* __restrict__ base) {
    int col0 = blockIdx.x * 128;
    int t = threadIdx.x;             // 128
    __shared__ float bt[NBB*128];
    __shared__ float at[BB*KK*NBB];
#pragma unroll
    for (int n = 0; n < NBB; n++) bt[n*128 + t] = base[(size_t)n*(FF*COUTT) + col0 + t];
    for (int i = t; i < BB*KK*NBB; i += 128) at[i] = g_attn[i];
    __syncthreads();
    for (int row = 0; row < BB*KK; row++) {
        float acc = 0.f;
#pragma unroll
        for (int n = 0; n < NBB; n++) acc += at[row*NBB + n]*bt[n*128 + t];
        g_wk[(size_t)row*(FF*COUTT) + col0 + t] = acc;
    }
}

// ---------------- cluster-grouped GEMM conv ----------------
__global__ void k_convg(float* __restrict__ out) {
    __shared__ float As[64*36];
    __shared__ float Ws[32*64];
    __shared__ int sgp[64];
    int bid = blockIdx.x;
    if (bid >= g_ntiles) return;
    int bk = g_tileBK[bid], m0 = g_tileM0[bid];
    int lo = g_off[bk];
    int rows = g_off[bk+1] - lo - m0;
    if (rows > 64) rows = 64;
    int t = threadIdx.x;             // 256
    if (t < 64) sgp[t] = (t < rows) ? g_plist[lo + m0 + t] : -1;
    __syncthreads();
    int tx = t & 15, ty = t >> 4;
    float acc[4][4];
#pragma unroll
    for (int i = 0; i < 4; i++)
#pragma unroll
        for (int j = 0; j < 4; j++) acc[i][j] = 0.f;
    const float* wkbase = g_wk + (size_t)bk * (FF*COUTT);
    for (int kc = 0; kc < FF; kc += 32) {
#pragma unroll
        for (int u = 0; u < 2; u++) {
            int idx = t + u*256;
            int r = idx >> 3, c4 = idx & 7;
            int gp = sgp[r];
            float4 v = make_float4(0.f, 0.f, 0.f, 0.f);
            if (gp >= 0) v = *(const float4*)(g_patches + (size_t)gp*FF + kc + c4*4);
            *(float4*)(As + r*36 + c4*4) = v;
        }
#pragma unroll
        for (int u = 0; u < 2; u++) {
            int idx = t + u*256;
            int j = idx >> 4, c4 = idx & 15;
            *(float4*)(Ws + j*64 + c4*4) = *(const float4*)(wkbase + (size_t)(kc + j)*COUTT + c4*4);
        }
        __syncthreads();
#pragma unroll
        for (int j = 0; j < 32; j++) {
            float a0 = As[(ty*4+0)*36 + j];
            float a1 = As[(ty*4+1)*36 + j];
            float a2 = As[(ty*4+2)*36 + j];
            float a3 = As[(ty*4+3)*36 + j];
            float4 w = *(const float4*)(Ws + j*64 + tx*4);
            acc[0][0] += a0*w.x; acc[0][1] += a0*w.y; acc[0][2] += a0*w.z; acc[0][3] += a0*w.w;
            acc[1][0] += a1*w.x; acc[1][1] += a1*w.y; acc[1][2] += a1*w.z; acc[1][3] += a1*w.w;
            acc[2][0] += a2*w.x; acc[2][1] += a2*w.y; acc[2][2] += a2*w.z; acc[2][3] += a2*w.w;
            acc[3][0] += a3*w.x; acc[3][1] += a3*w.y; acc[3][2] += a3*w.z; acc[3][3] += a3*w.w;
        }
        __syncthreads();
    }
    int b = bk >> 5;
    float4 bias = *(const float4*)(g_biasv + bk*COUTT + tx*4);
#pragma unroll
    for (int i = 0; i < 4; i++) {
        int gp = sgp[ty*4 + i];
        if (gp < 0) continue;
        int p = gp & 4095;
        size_t ob = (size_t)(b*COUTT + tx*4) * PP + p;
        out[ob          ] = acc[i][0] + bias.x;
        out[ob +   PP   ] = acc[i][1] + bias.y;
        out[ob + 2*PP   ] = acc[i][2] + bias.z;
        out[ob + 3*PP   ] = acc[i][3] + bias.w;
    }
}

// ---------------- launch ----------------
extern "C" void kernel_launch(void* const* d_in, const int* in_sizes, int n_in,
                              void* d_out, int out_size) {
    const float* x    = (const float*)d_in[0];
    const float* base = (const float*)d_in[1];
    const float* kw1 = (const float*)d_in[2];  const float* kb1 = (const float*)d_in[3];
    const float* kw2 = (const float*)d_in[4];  const float* kb2 = (const float*)d_in[5];
    const float* kw3 = (const float*)d_in[6];  const float* kb3 = (const float*)d_in[7];
    const float* bw1 = (const float*)d_in[8];  const float* bb1 = (const float*)d_in[9];
    const float* bw2 = (const float*)d_in[10]; const float* bb2 = (const float*)d_in[11];
    const float* bw3 = (const float*)d_in[12]; const float* bb3 = (const float*)d_in[13];
    float* out = (float*)d_out;

    // JAX key chain (partitionable/fold-like split): key(42) = (0,42)
    uint32_t bk0x, bk0y, bk1x, bk1y;
    threefry2x32(0u, 42u, 0u, 0u, bk0x, bk0y);   // batch 0 key
    threefry2x32(0u, 42u, 0u, 1u, bk1x, bk1y);   // batch 1 key
    uint4 s0, s1;
    {
        uint32_t c0, c1, u, v;
        threefry2x32(bk0x, bk0y, 0u, 1u, u, v); s0.x = u; s0.y = v;
        threefry2x32(bk0x, bk0y, 0u, 0u, c0, c1);
        threefry2x32(c0, c1, 0u, 1u, u, v);     s0.z = u; s0.w = v;
        threefry2x32(bk1x, bk1y, 0u, 1u, u, v); s1.x = u; s1.y = v;
        threefry2x32(bk1x, bk1y, 0u, 0u, c0, c1);
        threefry2x32(c0, c1, 0u, 1u, u, v);     s1.z = u; s1.w = v;
    }

    float* idx_out = (out_size >= BB*COUTT*PP + BB*PP) ? (out + BB*COUTT*PP) : nullptr;

    k_front<<<272, 1024>>>(x, s0, s1);
    k_seed<<<2, 1024>>>();
    k_kmeans<<<NBLK, 256>>>(idx_out, kw1, kb1, kw2, kb2, kw3, kb3,
                            bw1, bb1, bw2, bb2, bw3, bb3);
    k_wk<<<144, 128>>>(base);
    k_convg<<<MAXTILES, 256>>>(out);
}

// round 11
// speedup vs baseline: 1.1335x; 1.1335x over previous
#include <cuda_runtime.h>
#include <stdint.h>

#define BB 2
#define CC 32
#define HH 64
#define WW 64
#define PP 4096
#define FF 288
#define KK 32
#define NBB 32
#define HIDD 64
#define COUTT 64
#define NBLK 128      // persistent kmeans grid (64 blocks per batch)
#define MAXTILES 256
#define NSLOTS 48

// ---------------- device scratch (static, no allocation) ----------------
__device__ float    g_patches[BB*PP*FF];   // 9.4 MB
__device__ float    g_obs[BB*PP*CC];       // 1.0 MB
__device__ uint32_t g_rank[BB*2*PP];
__device__ int      g_permA[BB*PP];
__device__ int      g_initidx[BB*KK];
__device__ float    g_centers[BB*KK*CC];
__device__ float    g_part[NBLK][KK*CC + KK];   // per-block partials (no atomics)
__device__ float    g_shiftv[BB*KK];
__device__ int      g_cnt[BB*KK];
__device__ int      g_cursor[BB*KK];
__device__ int      g_off[BB*KK + 1];
__device__ int      g_plist[BB*PP];
__device__ int      g_tileBK[MAXTILES];
__device__ int      g_tileM0[MAXTILES];
__device__ int      g_ntiles;
__device__ float    g_attn[BB*KK*NBB];
__device__ float    g_biasv[BB*KK*COUTT];
__device__ float    g_wk[BB*KK*FF*COUTT];  // 4.7 MB
__device__ int      g_bslot[BB][NSLOTS];   // per-batch phase counters
__device__ int      g_gslot[4];            // global phase counters

// ---------------- Threefry-2x32 (JAX-compatible core) ----------------
__host__ __device__ inline void threefry2x32(uint32_t k0, uint32_t k1,
                                             uint32_t x0, uint32_t x1,
                                             uint32_t &o0, uint32_t &o1) {
    uint32_t ks2 = k0 ^ k1 ^ 0x1BD11BDAu;
    uint32_t v0 = x0 + k0, v1 = x1 + k1;
#define TF_R(r) { v0 += v1; v1 = (v1 << (r)) | (v1 >> (32 - (r))); v1 ^= v0; }
    TF_R(13) TF_R(15) TF_R(26) TF_R(6)   v0 += k1;  v1 += ks2 + 1u;
    TF_R(17) TF_R(29) TF_R(16) TF_R(24)  v0 += ks2; v1 += k0  + 2u;
    TF_R(13) TF_R(15) TF_R(26) TF_R(6)   v0 += k0;  v1 += k1  + 3u;
    TF_R(17) TF_R(29) TF_R(16) TF_R(24)  v0 += k1;  v1 += ks2 + 4u;
    TF_R(13) TF_R(15) TF_R(26) TF_R(6)   v0 += ks2; v1 += k0  + 5u;
#undef TF_R
    o0 = v0; o1 = v1;
}

// -------- barrier primitives: release-increment / acquire-poll ------------
__device__ __forceinline__ void bar_arrive(int* slot) {
    __syncthreads();
    if (threadIdx.x == 0) {
        asm volatile("red.release.gpu.global.add.s32 [%0], 1;"
                     :: "l"(slot) : "memory");
    }
}
__device__ __forceinline__ void bar_spin(int* slot, int target) {
    if (threadIdx.x == 0) {
        int v;
        do {
            asm volatile("ld.acquire.gpu.global.s32 %0, [%1];"
                         : "=r"(v) : "l"(slot) : "memory");
        } while (v < target);
    }
    __syncthreads();
}

// ---------------- unfold3 + channel-mean features (coalesced stores) ------
__global__ void k_prep(const float* __restrict__ x) {
    __shared__ float sbuf[4*FF];
    int warp = threadIdx.x >> 5, lane = threadIdx.x & 31;
    int gp = blockIdx.x * 4 + warp;           // 0..8191 = b*4096+p
    int b = gp >> 12, p = gp & 4095;
    int py = p >> 6, px = p & 63;
    const float* xc = x + (size_t)(b*CC + lane) * HH * WW;
    float* prow = sbuf + warp*FF + lane*9;
    float s = 0.f;
#pragma unroll
    for (int i = 0; i < 3; i++) {
        int yy = py + i - 1;
#pragma unroll
        for (int j = 0; j < 3; j++) {
            int xx = px + j - 1;
            float v = (yy >= 0 && yy < HH && xx >= 0 && xx < WW) ? xc[yy*WW + xx] : 0.f;
            prow[i*3 + j] = v;
            s += v;
        }
    }
    g_obs[(size_t)gp * CC + lane] = s / 9.f;
    __syncthreads();
    size_t base = (size_t)(blockIdx.x*4) * FF;
    for (int i = threadIdx.x; i < 4*FF; i += 128) g_patches[base + i] = sbuf[i];
}

// ---------------- bucket-based stable rank, keys fused in ------------------
__global__ void k_rankb(uint4 s0, uint4 s1) {
    int br = blockIdx.x;                 // 0..3 = b*2+r
    int b = br >> 1, r = br & 1;
    uint4 sk4 = b ? s1 : s0;
    uint32_t kk0 = r ? sk4.z : sk4.x;
    uint32_t kk1 = r ? sk4.w : sk4.y;
    __shared__ unsigned long long sorted[PP];   // 32 KB
    __shared__ int prefix[1025];
    __shared__ int cursor[1024];
    __shared__ int cnt[1024];
    __shared__ int wsum[32];
    int t = threadIdx.x;                 // 1024
    uint32_t kq[4];
#pragma unroll
    for (int q = 0; q < 4; q++) {
        uint32_t o0, o1;
        threefry2x32(kk0, kk1, 0u, (uint32_t)(t + q*1024), o0, o1);
        kq[q] = o0 ^ o1;
    }
    cnt[t] = 0;
    __syncthreads();
#pragma unroll
    for (int q = 0; q < 4; q++) atomicAdd(&cnt[kq[q] >> 22], 1);
    __syncthreads();
    int v = cnt[t];
    int lane = t & 31, wid = t >> 5;
    int s = v;
#pragma unroll
    for (int o = 1; o < 32; o <<= 1) { int u = __shfl_up_sync(0xffffffffu, s, o); if (lane >= o) s += u; }
    if (lane == 31) wsum[wid] = s;
    __syncthreads();
    if (wid == 0) {
        int ws = wsum[lane];
#pragma unroll
        for (int o = 1; o < 32; o <<= 1) { int u = __shfl_up_sync(0xffffffffu, ws, o); if (lane >= o) ws += u; }
        wsum[lane] = ws;
    }
    __syncthreads();
    int incl = s + (wid > 0 ? wsum[wid-1] : 0);
    prefix[t+1] = incl;
    if (t == 0) prefix[0] = 0;
    cursor[t] = incl - v;
    __syncthreads();
#pragma unroll
    for (int q = 0; q < 4; q++) {
        int p = atomicAdd(&cursor[kq[q] >> 22], 1);
        sorted[p] = ((unsigned long long)kq[q] << 32) | (uint32_t)(t + q*1024);
    }
    __syncthreads();
#pragma unroll
    for (int q = 0; q < 4; q++) {
        uint32_t key = kq[q];
        int i = t + q*1024;
        int bkt = key >> 22;
        int lo = prefix[bkt], hi = prefix[bkt+1];
        unsigned long long mine = ((unsigned long long)key << 32) | (uint32_t)i;
        int rr = lo;
        for (int j = lo; j < hi; j++) rr += (sorted[j] < mine) ? 1 : 0;
        g_rank[br*PP + i] = (uint32_t)rr;
    }
}

// ------- seed: global init + perm scatter + init-center gather (2 blocks) ---
__global__ void k_seed() {
    int b = blockIdx.x, t = threadIdx.x;   // 2 x 1024
    if (t < NSLOTS) g_bslot[b][t] = 0;
    if (b == 0 && t < 4) g_gslot[t] = 0;
    if (t < KK) { g_cnt[b*KK + t] = 0; g_cursor[b*KK + t] = 0; }
#pragma unroll
    for (int q = 0; q < 4; q++) {
        int i = t + q*1024;
        g_permA[b*PP + g_rank[(b*2)*PP + i]] = i;
    }
    __syncthreads();
#pragma unroll
    for (int q = 0; q < 4; q++) {
        int i = t + q*1024;
        uint32_t r1 = g_rank[(b*2+1)*PP + i];
        if (r1 < KK) g_initidx[b*KK + r1] = g_permA[b*PP + i];
    }
    __syncthreads();
    if (t < KK*CC) {
        int k = t >> 5, d = t & 31;
        g_centers[b*KK*CC + t] = g_obs[(size_t)(b*PP + g_initidx[b*KK + k])*CC + d];
    }
}

// --- persistent k-means + final assign + segmentation + sumsF + MLPs -------
__global__ void __launch_bounds__(128, 1) k_kmeans(
    float* idx_out,
    const float* __restrict__ kw1, const float* __restrict__ kb1,
    const float* __restrict__ kw2, const float* __restrict__ kb2,
    const float* __restrict__ kw3, const float* __restrict__ kb3,
    const float* __restrict__ bw1, const float* __restrict__ bb1,
    const float* __restrict__ bw2, const float* __restrict__ bb2,
    const float* __restrict__ bw3, const float* __restrict__ bb3)
{
    int bid = blockIdx.x;
    int b = bid >> 6;             // batch
    int sub = bid & 63;           // block within batch
    int t = threadIdx.x;          // 128
    int half = t & 1;
    int lp = t >> 1;              // local point 0..63
    int pi = sub*64 + lp;
    int lane = t & 31;
    int chunk = t >> 5;           // warp id 0..3
    int k0 = half * 16;
    __shared__ __align__(16) float sc[KK*CC];
    __shared__ __align__(16) float ssum[KK*CC];
    __shared__ float scn[KK];
    __shared__ float scnt[KK];
    __shared__ float sred[4][32];
    __shared__ float scred[64];
    __shared__ float s_sh;
    __shared__ int   soff[BB*KK + 1];

    // point features in registers (persist across all iterations)
    float s[CC]; float sn = 0.f;
    {
        const float* op = g_obs + (size_t)(b*PP + pi) * CC;
#pragma unroll
        for (int d = 0; d < CC; d++) { s[d] = op[d]; sn += s[d]*s[d]; }
    }
    for (int i = t; i < KK*CC; i += 128) sc[i] = __ldcg(&g_centers[b*KK*CC + i]);
    __syncthreads();

    for (int it = 0; it < 20; it++) {
        int phase = it * 2;
        for (int i = t; i < KK*CC; i += 128) ssum[i] = 0.f;
        if (t < KK) {
            scnt[t] = 0.f;
            float q = 0.f;
#pragma unroll
            for (int d = 0; d < CC; d++) { float c = sc[t*CC + d]; q += c*c; }
            scn[t] = q;
        }
        __syncthreads();
        // ---- assign: 16 clusters per thread, pair-combined ----
        float best = 3.4028235e38f; int bi = 0;
        for (int k = k0; k < k0 + 16; k++) {
            float dot = 0.f;
#pragma unroll
            for (int d = 0; d < CC; d += 4) {
                float4 c4 = *(const float4*)&sc[k*CC + d];
                dot += s[d]*c4.x; dot += s[d+1]*c4.y;
                dot += s[d+2]*c4.z; dot += s[d+3]*c4.w;
            }
            float d2 = sn - 2.0f*dot + scn[k];
            if (d2 < best) { best = d2; bi = k; }
        }
        {
            float ob = __shfl_xor_sync(0xffffffffu, best, 1);
            int   ok = __shfl_xor_sync(0xffffffffu, bi, 1);
            if (ob < best || (ob == best && ok < bi)) { best = ob; bi = ok; }
        }
        // ---- counts via ballot (no per-point atomics) ----
#pragma unroll
        for (int k = 0; k < KK; k++) {
            unsigned m = __ballot_sync(0xffffffffu, bi == k);
            if (lane == k && m) atomicAdd(&scnt[k], (float)__popc(m) * 0.5f);
        }
        // ---- conflict-free rotated smem accumulation ----
#pragma unroll
        for (int i = 0; i < 16; i++) {
            int d = k0 + ((i + lp) & 15);
            atomicAdd(&ssum[bi*CC + d], s[d]);
        }
        __syncthreads();
        // ---- flush private partial (plain stores, no global atomics) ----
        for (int i = t; i < KK*CC; i += 128) __stcg(&g_part[bid][i], ssum[i]);
        if (t < KK) __stcg(&g_part[bid][KK*CC + t], scnt[t]);
        bar_arrive(&g_bslot[b][phase]);
        // ---- reducers (sub<32): wait for all 64 partials, 4-way chunked ----
        if (sub < KK) {
            bar_spin(&g_bslot[b][phase], 64);
            float acc = 0.f;
            {
                int e = sub*CC + lane;
#pragma unroll
                for (int j = 0; j < 16; j++)
                    acc += __ldcg(&g_part[b*64 + chunk*16 + j][e]);
            }
            sred[chunk][lane] = acc;
            float cacc = (t < 64) ? __ldcg(&g_part[b*64 + t][KK*CC + sub]) : 0.f;
            __syncthreads();
            if (t < 64) scred[t] = cacc;
            __syncthreads();
            if (t < 32) {
                float tot = sred[0][t] + sred[1][t] + sred[2][t] + sred[3][t];
                // total count: reduce scred[0..63]
                float c2 = scred[t] + scred[t + 32];
#pragma unroll
                for (int o = 16; o > 0; o >>= 1) c2 += __shfl_xor_sync(0xffffffffu, c2, o);
                float cv = c2;
                float oldc = sc[sub*CC + t];
                float nv = (cv > 0.f) ? (tot / fmaxf(cv, 1.f)) : oldc;
                float d = nv - oldc;
                float q = d*d;
#pragma unroll
                for (int o = 16; o > 0; o >>= 1) q += __shfl_xor_sync(0xffffffffu, q, o);
                __stcg(&g_centers[b*KK*CC + sub*CC + t], nv);
                if (t == 0) __stcg(&g_shiftv[b*KK + sub], sqrtf(q));
            }
            bar_arrive(&g_bslot[b][phase + 1]);
        }
        // ---- everyone: wait for 32 reducers, reload centers + shift ----
        bar_spin(&g_bslot[b][phase + 1], 32);
        for (int i = t; i < KK*CC; i += 128) sc[i] = __ldcg(&g_centers[b*KK*CC + i]);
        if (t < KK) {
            float sv = __ldcg(&g_shiftv[b*KK + t]);
#pragma unroll
            for (int o = 16; o > 0; o >>= 1) sv += __shfl_xor_sync(0xffffffffu, sv, o);
            if (t == 0) s_sh = sv;
        }
        __syncthreads();
        if ((it + 1) >= 20 || s_sh < 20.48f) break;   // TOL*n = 0.005*4096
    }

    // ---- final assignment with converged centers ----
    if (t < KK) {
        float q = 0.f;
#pragma unroll
        for (int d = 0; d < CC; d++) { float c = sc[t*CC + d]; q += c*c; }
        scn[t] = q;
    }
    __syncthreads();
    float best = 3.4028235e38f; int bi = 0;
    for (int k = k0; k < k0 + 16; k++) {
        float dot = 0.f;
#pragma unroll
        for (int d = 0; d < CC; d += 4) {
            float4 c4 = *(const float4*)&sc[k*CC + d];
            dot += s[d]*c4.x; dot += s[d+1]*c4.y;
            dot += s[d+2]*c4.z; dot += s[d+3]*c4.w;
        }
        float d2 = sn - 2.0f*dot + scn[k];
        if (d2 < best) { best = d2; bi = k; }
    }
    {
        float ob = __shfl_xor_sync(0xffffffffu, best, 1);
        int   ok = __shfl_xor_sync(0xffffffffu, bi, 1);
        if (ob < best || (ob == best && ok < bi)) { best = ob; bi = ok; }
    }
    if (!half) {
        if (idx_out) __stcg(&idx_out[b*PP + pi], (float)bi);
        atomicAdd(&g_cnt[b*KK + bi], 1);
    }
    bar_arrive(&g_gslot[0]);
    bar_spin(&g_gslot[0], NBLK);
    // ---- offsets: every block computes redundantly via smem scan ----
    {
        int c = 0, sc_ = 0;
        if (t < BB*KK) {
            c = __ldcg(&g_cnt[t]);
            sc_ = c;
#pragma unroll
            for (int o = 1; o < 32; o <<= 1) {
                int u = __shfl_up_sync(0xffffffffu, sc_, o);
                if (lane >= o) sc_ += u;
            }
        }
        __shared__ int w0tot;
        if (t == 31) w0tot = sc_;
        __syncthreads();
        if (t >= 32 && t < 64) sc_ += w0tot;
        if (t < BB*KK) soff[t + 1] = sc_;
        if (t == 0) soff[0] = 0;
        __syncthreads();
    }
    // block 0 publishes g_off + tile list (needed by k_convg)
    if (bid == 0) {
        if (t <= BB*KK) g_off[t] = soff[t];
        if (t == 0) {
            int nt = 0;
            for (int bk = 0; bk < BB*KK; bk++) {
                int c = soff[bk+1] - soff[bk];
                for (int m = 0; m < c; m += 64) { g_tileBK[nt] = bk; g_tileM0[nt] = m; nt++; }
            }
            g_ntiles = nt;
        }
    }
    // ---- scatter pixel list ----
    if (!half) {
        int bk = b*KK + bi;
        int pos = soff[bk] + atomicAdd(&g_cursor[bk], 1);
        __stcg(&g_plist[pos], b*PP + pi);
    }
    bar_arrive(&g_gslot[1]);
    bar_spin(&g_gslot[1], NBLK);
    // ---- per-cluster 288-dim partial sums: 2 blocks per cluster ----
    {
        int bk = bid & 63, h = bid >> 6;
        int lo = soff[bk], hi = soff[bk+1];
        float a0 = 0.f, a1 = 0.f, a2 = 0.f;
        for (int m = lo + h; m < hi; m += 2) {
            int gp = __ldcg(&g_plist[m]);
            const float* pr = g_patches + (size_t)gp*FF;
            a0 += __ldcg(&pr[t]); a1 += __ldcg(&pr[t+128]);
            if (t < 32) a2 += __ldcg(&pr[t+256]);
        }
        __stcg(&g_part[bid][t], a0);
        __stcg(&g_part[bid][t+128], a1);
        if (t < 32) __stcg(&g_part[bid][t+256], a2);
    }
    bar_arrive(&g_gslot[2]);
    if (bid >= BB*KK) return;
    bar_spin(&g_gslot[2], NBLK);
    // ---- combine + the two tiny MLPs + softmax (blocks 0..63) ----
    {
        int bk = bid;
        __shared__ float cen[FF];
        __shared__ float h1[HIDD];
        __shared__ float h2[HIDD];
        float dv = fmaxf((float)(soff[bk+1] - soff[bk]), 1.f);
        cen[t]     = (__ldcg(&g_part[bk][t])     + __ldcg(&g_part[bk+64][t]))     / dv;
        cen[t+128] = (__ldcg(&g_part[bk][t+128]) + __ldcg(&g_part[bk+64][t+128])) / dv;
        if (t < 32)
            cen[t+256] = (__ldcg(&g_part[bk][t+256]) + __ldcg(&g_part[bk+64][t+256])) / dv;
        __syncthreads();
        if (t < HIDD) {
            float a = kb1[t];
            for (int f = 0; f < FF; f++) a += cen[f]*kw1[f*HIDD + t];
            h1[t] = fmaxf(a, 0.f);
        }
        __syncthreads();
        if (t < HIDD) {
            float a = kb2[t];
#pragma unroll
            for (int i = 0; i < HIDD; i++) a += h1[i]*kw2[i*HIDD + t];
            h2[t] = fmaxf(a, 0.f);
        }
        __syncthreads();
        if (t < NBB) {
            float a = kb3[t];
#pragma unroll
            for (int i = 0; i < HIDD; i++) a += h2[i]*kw3[i*NBB + t];
            float m = a;
#pragma unroll
            for (int off = 16; off > 0; off >>= 1) m = fmaxf(m, __shfl_xor_sync(0xffffffffu, m, off));
            float e = expf(a - m);
            float ss = e;
#pragma unroll
            for (int off = 16; off > 0; off >>= 1) ss += __shfl_xor_sync(0xffffffffu, ss, off);
            g_attn[bk*NBB + t] = e / ss;
        }
        __syncthreads();
        if (t < HIDD) {
            float a = bb1[t];
            for (int f = 0; f < FF; f++) a += cen[f]*bw1[f*HIDD + t];
            h1[t] = fmaxf(a, 0.f);
        }
        __syncthreads();
        if (t < HIDD) {
            float a = bb2[t];
#pragma unroll
            for (int i = 0; i < HIDD; i++) a += h1[i]*bw2[i*HIDD + t];
            h2[t] = fmaxf(a, 0.f);
        }
        __syncthreads();
        if (t < COUTT) {
            float a = bb3[t];
#pragma unroll
            for (int i = 0; i < HIDD; i++) a += h2[i]*bw3[i*COUTT + t];
            g_biasv[bk*COUTT + t] = a;
        }
    }
}

// ---------------- kernels = attn @ base_kernels (row-split, 512 thr) -------
__global__ void k_wk(const float* __restrict__ base) {
    int col0 = blockIdx.x * 128;
    int t = threadIdx.x;             // 512
    int tc = t & 127;                // column within group
    int tr = t >> 7;                 // row group 0..3 (16 rows each)
    __shared__ float bt[NBB*128];
    __shared__ float at[BB*KK*NBB];
    for (int i = t; i < NBB*128; i += 512)
        bt[i] = base[(size_t)(i >> 7)*(FF*COUTT) + col0 + (i & 127)];
    for (int i = t; i < BB*KK*NBB; i += 512) at[i] = g_attn[i];
    __syncthreads();
#pragma unroll
    for (int rr = 0; rr < 16; rr++) {
        int row = tr*16 + rr;
        float acc = 0.f;
#pragma unroll
        for (int n = 0; n < NBB; n++) acc += at[row*NBB + n]*bt[n*128 + tc];
        g_wk[(size_t)row*(FF*COUTT) + col0 + tc] = acc;
    }
}

// ---------------- cluster-grouped GEMM conv ----------------
__global__ void k_convg(float* __restrict__ out) {
    __shared__ float As[64*36];
    __shared__ float Ws[32*64];
    __shared__ int sgp[64];
    int bid = blockIdx.x;
    if (bid >= g_ntiles) return;
    int bk = g_tileBK[bid], m0 = g_tileM0[bid];
    int lo = g_off[bk];
    int rows = g_off[bk+1] - lo - m0;
    if (rows > 64) rows = 64;
    int t = threadIdx.x;             // 256
    if (t < 64) sgp[t] = (t < rows) ? g_plist[lo + m0 + t] : -1;
    __syncthreads();
    int tx = t & 15, ty = t >> 4;
    float acc[4][4];
#pragma unroll
    for (int i = 0; i < 4; i++)
#pragma unroll
        for (int j = 0; j < 4; j++) acc[i][j] = 0.f;
    const float* wkbase = g_wk + (size_t)bk * (FF*COUTT);
    for (int kc = 0; kc < FF; kc += 32) {
#pragma unroll
        for (int u = 0; u < 2; u++) {
            int idx = t + u*256;
            int r = idx >> 3, c4 = idx & 7;
            int gp = sgp[r];
            float4 v = make_float4(0.f, 0.f, 0.f, 0.f);
            if (gp >= 0) v = *(const float4*)(g_patches + (size_t)gp*FF + kc + c4*4);
            *(float4*)(As + r*36 + c4*4) = v;
        }
#pragma unroll
        for (int u = 0; u < 2; u++) {
            int idx = t + u*256;
            int j = idx >> 4, c4 = idx & 15;
            *(float4*)(Ws + j*64 + c4*4) = *(const float4*)(wkbase + (size_t)(kc + j)*COUTT + c4*4);
        }
        __syncthreads();
#pragma unroll
        for (int j = 0; j < 32; j++) {
            float a0 = As[(ty*4+0)*36 + j];
            float a1 = As[(ty*4+1)*36 + j];
            float a2 = As[(ty*4+2)*36 + j];
            float a3 = As[(ty*4+3)*36 + j];
            float4 w = *(const float4*)(Ws + j*64 + tx*4);
            acc[0][0] += a0*w.x; acc[0][1] += a0*w.y; acc[0][2] += a0*w.z; acc[0][3] += a0*w.w;
            acc[1][0] += a1*w.x; acc[1][1] += a1*w.y; acc[1][2] += a1*w.z; acc[1][3] += a1*w.w;
            acc[2][0] += a2*w.x; acc[2][1] += a2*w.y; acc[2][2] += a2*w.z; acc[2][3] += a2*w.w;
            acc[3][0] += a3*w.x; acc[3][1] += a3*w.y; acc[3][2] += a3*w.z; acc[3][3] += a3*w.w;
        }
        __syncthreads();
    }
    int b = bk >> 5;
    float4 bias = *(const float4*)(g_biasv + bk*COUTT + tx*4);
#pragma unroll
    for (int i = 0; i < 4; i++) {
        int gp = sgp[ty*4 + i];
        if (gp < 0) continue;
        int p = gp & 4095;
        size_t ob = (size_t)(b*COUTT + tx*4) * PP + p;
        out[ob          ] = acc[i][0] + bias.x;
        out[ob +   PP   ] = acc[i][1] + bias.y;
        out[ob + 2*PP   ] = acc[i][2] + bias.z;
        out[ob + 3*PP   ] = acc[i][3] + bias.w;
    }
}

// ---------------- launch ----------------
extern "C" void kernel_launch(void* const* d_in, const int* in_sizes, int n_in,
                              void* d_out, int out_size) {
    const float* x    = (const float*)d_in[0];
    const float* base = (const float*)d_in[1];
    const float* kw1 = (const float*)d_in[2];  const float* kb1 = (const float*)d_in[3];
    const float* kw2 = (const float*)d_in[4];  const float* kb2 = (const float*)d_in[5];
    const float* kw3 = (const float*)d_in[6];  const float* kb3 = (const float*)d_in[7];
    const float* bw1 = (const float*)d_in[8];  const float* bb1 = (const float*)d_in[9];
    const float* bw2 = (const float*)d_in[10]; const float* bb2 = (const float*)d_in[11];
    const float* bw3 = (const float*)d_in[12]; const float* bb3 = (const float*)d_in[13];
    float* out = (float*)d_out;

    // JAX key chain (partitionable/fold-like split): key(42) = (0,42)
    uint32_t bk0x, bk0y, bk1x, bk1y;
    threefry2x32(0u, 42u, 0u, 0u, bk0x, bk0y);   // batch 0 key
    threefry2x32(0u, 42u, 0u, 1u, bk1x, bk1y);   // batch 1 key
    uint4 s0, s1;
    {
        uint32_t c0, c1, u, v;
        threefry2x32(bk0x, bk0y, 0u, 1u, u, v); s0.x = u; s0.y = v;
        threefry2x32(bk0x, bk0y, 0u, 0u, c0, c1);
        threefry2x32(c0, c1, 0u, 1u, u, v);     s0.z = u; s0.w = v;
        threefry2x32(bk1x, bk1y, 0u, 1u, u, v); s1.x = u; s1.y = v;
        threefry2x32(bk1x, bk1y, 0u, 0u, c0, c1);
        threefry2x32(c0, c1, 0u, 1u, u, v);     s1.z = u; s1.w = v;
    }

    float* idx_out = (out_size >= BB*COUTT*PP + BB*PP) ? (out + BB*COUTT*PP) : nullptr;

    k_prep<<<2048, 128>>>(x);
    k_rankb<<<4, 1024>>>(s0, s1);
    k_seed<<<2, 1024>>>();
    k_kmeans<<<NBLK, 128>>>(idx_out, kw1, kb1, kw2, kb2, kw3, kb3,
                            bw1, bb1, bw2, bb2, bw3, bb3);
    k_wk<<<144, 512>>>(base);
    k_convg<<<MAXTILES, 256>>>(out);
}

// round 12
// speedup vs baseline: 1.1338x; 1.0002x over previous
#include <cuda_runtime.h>
#include <stdint.h>

#define BB 2
#define CC 32
#define HH 64
#define WW 64
#define PP 4096
#define FF 288
#define KK 32
#define NBB 32
#define HIDD 64
#define COUTT 64
#define NBLK 128      // persistent kmeans grid (64 blocks per batch)
#define MAXTILES 256
#define NSLOTS 48

// ---------------- device scratch (static, no allocation) ----------------
__device__ float    g_patches[BB*PP*FF];   // 9.4 MB
__device__ float    g_obs[BB*PP*CC];       // 1.0 MB
__device__ uint32_t g_rank[BB*2*PP];
__device__ int      g_permA[BB*PP];
__device__ int      g_initidx[BB*KK];
__device__ float    g_centers[BB*KK*CC];
__device__ float    g_part[NBLK][KK*CC + KK];   // per-block partials (no atomics)
__device__ float    g_shiftv[BB*KK];
__device__ int      g_cnt[BB*KK];
__device__ int      g_cursor[BB*KK];
__device__ int      g_off[BB*KK + 1];
__device__ int      g_plist[BB*PP];
__device__ int      g_tileBK[MAXTILES];
__device__ int      g_tileM0[MAXTILES];
__device__ int      g_ntiles;
__device__ float    g_attn[BB*KK*NBB];
__device__ float    g_biasv[BB*KK*COUTT];
__device__ float    g_wk[BB*KK*FF*COUTT];  // 4.7 MB
__device__ int      g_bslot[BB][NSLOTS];   // per-batch phase counters
__device__ int      g_gslot[4];            // global phase counters

// ---------------- Threefry-2x32 (JAX-compatible core) ----------------
__host__ __device__ inline void threefry2x32(uint32_t k0, uint32_t k1,
                                             uint32_t x0, uint32_t x1,
                                             uint32_t &o0, uint32_t &o1) {
    uint32_t ks2 = k0 ^ k1 ^ 0x1BD11BDAu;
    uint32_t v0 = x0 + k0, v1 = x1 + k1;
#define TF_R(r) { v0 += v1; v1 = (v1 << (r)) | (v1 >> (32 - (r))); v1 ^= v0; }
    TF_R(13) TF_R(15) TF_R(26) TF_R(6)   v0 += k1;  v1 += ks2 + 1u;
    TF_R(17) TF_R(29) TF_R(16) TF_R(24)  v0 += ks2; v1 += k0  + 2u;
    TF_R(13) TF_R(15) TF_R(26) TF_R(6)   v0 += k0;  v1 += k1  + 3u;
    TF_R(17) TF_R(29) TF_R(16) TF_R(24)  v0 += k1;  v1 += ks2 + 4u;
    TF_R(13) TF_R(15) TF_R(26) TF_R(6)   v0 += ks2; v1 += k0  + 5u;
#undef TF_R
    o0 = v0; o1 = v1;
}

// -------- barrier primitives: release-increment / acquire-poll ------------
__device__ __forceinline__ void bar_arrive(int* slot) {
    __syncthreads();
    if (threadIdx.x == 0) {
        asm volatile("red.release.gpu.global.add.s32 [%0], 1;"
                     :: "l"(slot) : "memory");
    }
}
__device__ __forceinline__ void bar_spin(int* slot, int target) {
    if (threadIdx.x == 0) {
        int v;
        do {
            asm volatile("ld.acquire.gpu.global.s32 %0, [%1];"
                         : "=r"(v) : "l"(slot) : "memory");
        } while (v < target);
    }
    __syncthreads();
}

// ---------------- unfold3 + channel-mean features (coalesced stores) ------
__global__ void k_prep(const float* __restrict__ x) {
    __shared__ float sbuf[4*FF];
    int warp = threadIdx.x >> 5, lane = threadIdx.x & 31;
    int gp = blockIdx.x * 4 + warp;           // 0..8191 = b*4096+p
    int b = gp >> 12, p = gp & 4095;
    int py = p >> 6, px = p & 63;
    const float* xc = x + (size_t)(b*CC + lane) * HH * WW;
    float* prow = sbuf + warp*FF + lane*9;
    float s = 0.f;
#pragma unroll
    for (int i = 0; i < 3; i++) {
        int yy = py + i - 1;
#pragma unroll
        for (int j = 0; j < 3; j++) {
            int xx = px + j - 1;
            float v = (yy >= 0 && yy < HH && xx >= 0 && xx < WW) ? xc[yy*WW + xx] : 0.f;
            prow[i*3 + j] = v;
            s += v;
        }
    }
    g_obs[(size_t)gp * CC + lane] = s / 9.f;
    __syncthreads();
    size_t base = (size_t)(blockIdx.x*4) * FF;
    for (int i = threadIdx.x; i < 4*FF; i += 128) g_patches[base + i] = sbuf[i];
}

// ---------------- bucket-based stable rank, keys fused in ------------------
__global__ void k_rankb(uint4 s0, uint4 s1) {
    int br = blockIdx.x;                 // 0..3 = b*2+r
    int b = br >> 1, r = br & 1;
    uint4 sk4 = b ? s1 : s0;
    uint32_t kk0 = r ? sk4.z : sk4.x;
    uint32_t kk1 = r ? sk4.w : sk4.y;
    __shared__ unsigned long long sorted[PP];   // 32 KB
    __shared__ int prefix[1025];
    __shared__ int cursor[1024];
    __shared__ int cnt[1024];
    __shared__ int wsum[32];
    int t = threadIdx.x;                 // 1024
    uint32_t kq[4];
#pragma unroll
    for (int q = 0; q < 4; q++) {
        uint32_t o0, o1;
        threefry2x32(kk0, kk1, 0u, (uint32_t)(t + q*1024), o0, o1);
        kq[q] = o0 ^ o1;
    }
    cnt[t] = 0;
    __syncthreads();
#pragma unroll
    for (int q = 0; q < 4; q++) atomicAdd(&cnt[kq[q] >> 22], 1);
    __syncthreads();
    int v = cnt[t];
    int lane = t & 31, wid = t >> 5;
    int s = v;
#pragma unroll
    for (int o = 1; o < 32; o <<= 1) { int u = __shfl_up_sync(0xffffffffu, s, o); if (lane >= o) s += u; }
    if (lane == 31) wsum[wid] = s;
    __syncthreads();
    if (wid == 0) {
        int ws = wsum[lane];
#pragma unroll
        for (int o = 1; o < 32; o <<= 1) { int u = __shfl_up_sync(0xffffffffu, ws, o); if (lane >= o) ws += u; }
        wsum[lane] = ws;
    }
    __syncthreads();
    int incl = s + (wid > 0 ? wsum[wid-1] : 0);
    prefix[t+1] = incl;
    if (t == 0) prefix[0] = 0;
    cursor[t] = incl - v;
    __syncthreads();
#pragma unroll
    for (int q = 0; q < 4; q++) {
        int p = atomicAdd(&cursor[kq[q] >> 22], 1);
        sorted[p] = ((unsigned long long)kq[q] << 32) | (uint32_t)(t + q*1024);
    }
    __syncthreads();
#pragma unroll
    for (int q = 0; q < 4; q++) {
        uint32_t key = kq[q];
        int i = t + q*1024;
        int bkt = key >> 22;
        int lo = prefix[bkt], hi = prefix[bkt+1];
        unsigned long long mine = ((unsigned long long)key << 32) | (uint32_t)i;
        int rr = lo;
        for (int j = lo; j < hi; j++) rr += (sorted[j] < mine) ? 1 : 0;
        g_rank[br*PP + i] = (uint32_t)rr;
    }
}

// ------- seed: global init + perm scatter + init-center gather (2 blocks) ---
__global__ void k_seed() {
    int b = blockIdx.x, t = threadIdx.x;   // 2 x 1024
    if (t < NSLOTS) g_bslot[b][t] = 0;
    if (b == 0 && t < 4) g_gslot[t] = 0;
    if (t < KK) { g_cnt[b*KK + t] = 0; g_cursor[b*KK + t] = 0; }
#pragma unroll
    for (int q = 0; q < 4; q++) {
        int i = t + q*1024;
        g_permA[b*PP + g_rank[(b*2)*PP + i]] = i;
    }
    __syncthreads();
#pragma unroll
    for (int q = 0; q < 4; q++) {
        int i = t + q*1024;
        uint32_t r1 = g_rank[(b*2+1)*PP + i];
        if (r1 < KK) g_initidx[b*KK + r1] = g_permA[b*PP + i];
    }
    __syncthreads();
    if (t < KK*CC) {
        int k = t >> 5, d = t & 31;
        g_centers[b*KK*CC + t] = g_obs[(size_t)(b*PP + g_initidx[b*KK + k])*CC + d];
    }
}

// --- persistent k-means + final assign + segmentation + sumsF + MLPs -------
__global__ void __launch_bounds__(128, 1) k_kmeans(
    float* idx_out,
    const float* __restrict__ kw1, const float* __restrict__ kb1,
    const float* __restrict__ kw2, const float* __restrict__ kb2,
    const float* __restrict__ kw3, const float* __restrict__ kb3,
    const float* __restrict__ bw1, const float* __restrict__ bb1,
    const float* __restrict__ bw2, const float* __restrict__ bb2,
    const float* __restrict__ bw3, const float* __restrict__ bb3)
{
    int bid = blockIdx.x;
    int b = bid >> 6;             // batch
    int sub = bid & 63;           // block within batch
    int t = threadIdx.x;          // 128
    int half = t & 1;
    int lp = t >> 1;              // local point 0..63
    int pi = sub*64 + lp;
    int lane = t & 31;
    int chunk = t >> 5;           // warp id 0..3
    int k0 = half * 16;
    __shared__ __align__(16) float sc[KK*CC];
    __shared__ __align__(16) float ssum4[4][KK*CC];   // per-warp-group partials
    __shared__ __align__(16) float sfeat[64*33];      // staged point features
    __shared__ int   slab[64];
    __shared__ float scn[KK];
    __shared__ float scnt[KK];
    __shared__ float sred[4][32];
    __shared__ float scred[64];
    __shared__ float s_sh;
    __shared__ int   soff[BB*KK + 1];

    // point features in registers (persist across all iterations)
    float s[CC]; float sn = 0.f;
    {
        const float* op = g_obs + (size_t)(b*PP + pi) * CC;
#pragma unroll
        for (int d = 0; d < CC; d++) { s[d] = op[d]; sn += s[d]*s[d]; }
    }
    // stage features to padded smem once (conflict-free)
#pragma unroll
    for (int i = 0; i < 16; i++) sfeat[lp*33 + k0 + i] = s[k0 + i];
    for (int i = t; i < KK*CC; i += 128) sc[i] = __ldcg(&g_centers[b*KK*CC + i]);
    __syncthreads();

    int ad = t & 31;              // accumulation dim
    int ag = t >> 5;              // accumulation group (warp)

    for (int it = 0; it < 20; it++) {
        int phase = it * 2;
        for (int i = t; i < 4*KK*CC; i += 128) ssum4[0][i] = 0.f;
        if (t < KK) {
            scnt[t] = 0.f;
            float q = 0.f;
#pragma unroll
            for (int d = 0; d < CC; d++) { float c = sc[t*CC + d]; q += c*c; }
            scn[t] = q;
        }
        __syncthreads();
        // ---- assign: 16 clusters per thread, pair-combined ----
        float best = 3.4028235e38f; int bi = 0;
        for (int k = k0; k < k0 + 16; k++) {
            float dot = 0.f;
#pragma unroll
            for (int d = 0; d < CC; d += 4) {
                float4 c4 = *(const float4*)&sc[k*CC + d];
                dot += s[d]*c4.x; dot += s[d+1]*c4.y;
                dot += s[d+2]*c4.z; dot += s[d+3]*c4.w;
            }
            float d2 = sn - 2.0f*dot + scn[k];
            if (d2 < best) { best = d2; bi = k; }
        }
        {
            float ob = __shfl_xor_sync(0xffffffffu, best, 1);
            int   ok = __shfl_xor_sync(0xffffffffu, bi, 1);
            if (ob < best || (ob == best && ok < bi)) { best = ob; bi = ok; }
        }
        // ---- counts via ballot + publish labels ----
#pragma unroll
        for (int k = 0; k < KK; k++) {
            unsigned m = __ballot_sync(0xffffffffu, bi == k);
            if (lane == k && m) atomicAdd(&scnt[k], (float)__popc(m) * 0.5f);
        }
        if (!half) slab[lp] = bi;
        __syncthreads();
        // ---- transposed accumulation: NO atomics, exclusive (g,d) columns --
        {
            float* acc = ssum4[ag];
            int p0 = ag * 16;
#pragma unroll
            for (int p = 0; p < 16; p++) {
                int lab = slab[p0 + p];
                float v = sfeat[(p0 + p)*33 + ad];
                acc[lab*CC + ad] += v;
            }
        }
        __syncthreads();
        // ---- flush combined partial (fixed group order, deterministic) ----
        for (int i = t; i < KK*CC; i += 128)
            __stcg(&g_part[bid][i],
                   ssum4[0][i] + ssum4[1][i] + ssum4[2][i] + ssum4[3][i]);
        if (t < KK) __stcg(&g_part[bid][KK*CC + t], scnt[t]);
        bar_arrive(&g_bslot[b][phase]);
        // ---- reducers (sub<32): wait for all 64 partials, 4-way chunked ----
        if (sub < KK) {
            bar_spin(&g_bslot[b][phase], 64);
            float acc = 0.f;
            {
                int e = sub*CC + lane;
#pragma unroll
                for (int j = 0; j < 16; j++)
                    acc += __ldcg(&g_part[b*64 + chunk*16 + j][e]);
            }
            sred[chunk][lane] = acc;
            float cacc = (t < 64) ? __ldcg(&g_part[b*64 + t][KK*CC + sub]) : 0.f;
            __syncthreads();
            if (t < 64) scred[t] = cacc;
            __syncthreads();
            if (t < 32) {
                float tot = sred[0][t] + sred[1][t] + sred[2][t] + sred[3][t];
                float c2 = scred[t] + scred[t + 32];
#pragma unroll
                for (int o = 16; o > 0; o >>= 1) c2 += __shfl_xor_sync(0xffffffffu, c2, o);
                float cv = c2;
                float oldc = sc[sub*CC + t];
                float nv = (cv > 0.f) ? (tot / fmaxf(cv, 1.f)) : oldc;
                float d = nv - oldc;
                float q = d*d;
#pragma unroll
                for (int o = 16; o > 0; o >>= 1) q += __shfl_xor_sync(0xffffffffu, q, o);
                __stcg(&g_centers[b*KK*CC + sub*CC + t], nv);
                if (t == 0) __stcg(&g_shiftv[b*KK + sub], sqrtf(q));
            }
            bar_arrive(&g_bslot[b][phase + 1]);
        }
        // ---- everyone: wait for 32 reducers, reload centers + shift ----
        bar_spin(&g_bslot[b][phase + 1], 32);
        for (int i = t; i < KK*CC; i += 128) sc[i] = __ldcg(&g_centers[b*KK*CC + i]);
        if (t < KK) {
            float sv = __ldcg(&g_shiftv[b*KK + t]);
#pragma unroll
            for (int o = 16; o > 0; o >>= 1) sv += __shfl_xor_sync(0xffffffffu, sv, o);
            if (t == 0) s_sh = sv;
        }
        __syncthreads();
        if ((it + 1) >= 20 || s_sh < 20.48f) break;   // TOL*n = 0.005*4096
    }

    // ---- final assignment with converged centers ----
    if (t < KK) {
        float q = 0.f;
#pragma unroll
        for (int d = 0; d < CC; d++) { float c = sc[t*CC + d]; q += c*c; }
        scn[t] = q;
    }
    __syncthreads();
    float best = 3.4028235e38f; int bi = 0;
    for (int k = k0; k < k0 + 16; k++) {
        float dot = 0.f;
#pragma unroll
        for (int d = 0; d < CC; d += 4) {
            float4 c4 = *(const float4*)&sc[k*CC + d];
            dot += s[d]*c4.x; dot += s[d+1]*c4.y;
            dot += s[d+2]*c4.z; dot += s[d+3]*c4.w;
        }
        float d2 = sn - 2.0f*dot + scn[k];
        if (d2 < best) { best = d2; bi = k; }
    }
    {
        float ob = __shfl_xor_sync(0xffffffffu, best, 1);
        int   ok = __shfl_xor_sync(0xffffffffu, bi, 1);
        if (ob < best || (ob == best && ok < bi)) { best = ob; bi = ok; }
    }
    if (!half) {
        if (idx_out) __stcg(&idx_out[b*PP + pi], (float)bi);
        atomicAdd(&g_cnt[b*KK + bi], 1);
    }
    bar_arrive(&g_gslot[0]);
    bar_spin(&g_gslot[0], NBLK);
    // ---- offsets: every block computes redundantly via smem scan ----
    {
        int c = 0, sc_ = 0;
        if (t < BB*KK) {
            c = __ldcg(&g_cnt[t]);
            sc_ = c;
#pragma unroll
            for (int o = 1; o < 32; o <<= 1) {
                int u = __shfl_up_sync(0xffffffffu, sc_, o);
                if (lane >= o) sc_ += u;
            }
        }
        __shared__ int w0tot;
        if (t == 31) w0tot = sc_;
        __syncthreads();
        if (t >= 32 && t < 64) sc_ += w0tot;
        if (t < BB*KK) soff[t + 1] = sc_;
        if (t == 0) soff[0] = 0;
        __syncthreads();
    }
    // block 0 publishes g_off + tile list (needed by k_convg)
    if (bid == 0) {
        if (t <= BB*KK) g_off[t] = soff[t];
        if (t == 0) {
            int nt = 0;
            for (int bk = 0; bk < BB*KK; bk++) {
                int c = soff[bk+1] - soff[bk];
                for (int m = 0; m < c; m += 64) { g_tileBK[nt] = bk; g_tileM0[nt] = m; nt++; }
            }
            g_ntiles = nt;
        }
    }
    // ---- scatter pixel list ----
    if (!half) {
        int bk = b*KK + bi;
        int pos = soff[bk] + atomicAdd(&g_cursor[bk], 1);
        __stcg(&g_plist[pos], b*PP + pi);
    }
    bar_arrive(&g_gslot[1]);
    bar_spin(&g_gslot[1], NBLK);
    // ---- per-cluster 288-dim partial sums: 2 blocks per cluster ----
    {
        int bk = bid & 63, h = bid >> 6;
        int lo = soff[bk], hi = soff[bk+1];
        float a0 = 0.f, a1 = 0.f, a2 = 0.f;
        for (int m = lo + h; m < hi; m += 2) {
            int gp = __ldcg(&g_plist[m]);
            const float* pr = g_patches + (size_t)gp*FF;
            a0 += __ldcg(&pr[t]); a1 += __ldcg(&pr[t+128]);
            if (t < 32) a2 += __ldcg(&pr[t+256]);
        }
        __stcg(&g_part[bid][t], a0);
        __stcg(&g_part[bid][t+128], a1);
        if (t < 32) __stcg(&g_part[bid][t+256], a2);
    }
    bar_arrive(&g_gslot[2]);
    if (bid >= BB*KK) return;
    bar_spin(&g_gslot[2], NBLK);
    // ---- combine + the two tiny MLPs + softmax (blocks 0..63) ----
    {
        int bk = bid;
        __shared__ float cen[FF];
        __shared__ float h1[HIDD];
        __shared__ float h2[HIDD];
        float dv = fmaxf((float)(soff[bk+1] - soff[bk]), 1.f);
        cen[t]     = (__ldcg(&g_part[bk][t])     + __ldcg(&g_part[bk+64][t]))     / dv;
        cen[t+128] = (__ldcg(&g_part[bk][t+128]) + __ldcg(&g_part[bk+64][t+128])) / dv;
        if (t < 32)
            cen[t+256] = (__ldcg(&g_part[bk][t+256]) + __ldcg(&g_part[bk+64][t+256])) / dv;
        __syncthreads();
        if (t < HIDD) {
            float a = kb1[t];
            for (int f = 0; f < FF; f++) a += cen[f]*kw1[f*HIDD + t];
            h1[t] = fmaxf(a, 0.f);
        }
        __syncthreads();
        if (t < HIDD) {
            float a = kb2[t];
#pragma unroll
            for (int i = 0; i < HIDD; i++) a += h1[i]*kw2[i*HIDD + t];
            h2[t] = fmaxf(a, 0.f);
        }
        __syncthreads();
        if (t < NBB) {
            float a = kb3[t];
#pragma unroll
            for (int i = 0; i < HIDD; i++) a += h2[i]*kw3[i*NBB + t];
            float m = a;
#pragma unroll
            for (int off = 16; off > 0; off >>= 1) m = fmaxf(m, __shfl_xor_sync(0xffffffffu, m, off));
            float e = expf(a - m);
            float ss = e;
#pragma unroll
            for (int off = 16; off > 0; off >>= 1) ss += __shfl_xor_sync(0xffffffffu, ss, off);
            g_attn[bk*NBB + t] = e / ss;
        }
        __syncthreads();
        if (t < HIDD) {
            float a = bb1[t];
            for (int f = 0; f < FF; f++) a += cen[f]*bw1[f*HIDD + t];
            h1[t] = fmaxf(a, 0.f);
        }
        __syncthreads();
        if (t < HIDD) {
            float a = bb2[t];
#pragma unroll
            for (int i = 0; i < HIDD; i++) a += h1[i]*bw2[i*HIDD + t];
            h2[t] = fmaxf(a, 0.f);
        }
        __syncthreads();
        if (t < COUTT) {
            float a = bb3[t];
#pragma unroll
            for (int i = 0; i < HIDD; i++) a += h2[i]*bw3[i*COUTT + t];
            g_biasv[bk*COUTT + t] = a;
        }
    }
}

// ---------------- kernels = attn @ base_kernels (row-split, 512 thr) -------
__global__ void k_wk(const float* __restrict__ base) {
    int col0 = blockIdx.x * 128;
    int t = threadIdx.x;             // 512
    int tc = t & 127;                // column within group
    int tr = t >> 7;                 // row group 0..3 (16 rows each)
    __shared__ float bt[NBB*128];
    __shared__ float at[BB*KK*NBB];
    for (int i = t; i < NBB*128; i += 512)
        bt[i] = base[(size_t)(i >> 7)*(FF*COUTT) + col0 + (i & 127)];
    for (int i = t; i < BB*KK*NBB; i += 512) at[i] = g_attn[i];
    __syncthreads();
#pragma unroll
    for (int rr = 0; rr < 16; rr++) {
        int row = tr*16 + rr;
        float acc = 0.f;
#pragma unroll
        for (int n = 0; n < NBB; n++) acc += at[row*NBB + n]*bt[n*128 + tc];
        g_wk[(size_t)row*(FF*COUTT) + col0 + tc] = acc;
    }
}

// ---------------- cluster-grouped GEMM conv ----------------
__global__ void k_convg(float* __restrict__ out) {
    __shared__ float As[64*36];
    __shared__ float Ws[32*64];
    __shared__ int sgp[64];
    int bid = blockIdx.x;
    if (bid >= g_ntiles) return;
    int bk = g_tileBK[bid], m0 = g_tileM0[bid];
    int lo = g_off[bk];
    int rows = g_off[bk+1] - lo - m0;
    if (rows > 64) rows = 64;
    int t = threadIdx.x;             // 256
    if (t < 64) sgp[t] = (t < rows) ? g_plist[lo + m0 + t] : -1;
    __syncthreads();
    int tx = t & 15, ty = t >> 4;
    float acc[4][4];
#pragma unroll
    for (int i = 0; i < 4; i++)
#pragma unroll
        for (int j = 0; j < 4; j++) acc[i][j] = 0.f;
    const float* wkbase = g_wk + (size_t)bk * (FF*COUTT);
    for (int kc = 0; kc < FF; kc += 32) {
#pragma unroll
        for (int u = 0; u < 2; u++) {
            int idx = t + u*256;
            int r = idx >> 3, c4 = idx & 7;
            int gp = sgp[r];
            float4 v = make_float4(0.f, 0.f, 0.f, 0.f);
            if (gp >= 0) v = *(const float4*)(g_patches + (size_t)gp*FF + kc + c4*4);
            *(float4*)(As + r*36 + c4*4) = v;
        }
#pragma unroll
        for (int u = 0; u < 2; u++) {
            int idx = t + u*256;
            int j = idx >> 4, c4 = idx & 15;
            *(float4*)(Ws + j*64 + c4*4) = *(const float4*)(wkbase + (size_t)(kc + j)*COUTT + c4*4);
        }
        __syncthreads();
#pragma unroll
        for (int j = 0; j < 32; j++) {
            float a0 = As[(ty*4+0)*36 + j];
            float a1 = As[(ty*4+1)*36 + j];
            float a2 = As[(ty*4+2)*36 + j];
            float a3 = As[(ty*4+3)*36 + j];
            float4 w = *(const float4*)(Ws + j*64 + tx*4);
            acc[0][0] += a0*w.x; acc[0][1] += a0*w.y; acc[0][2] += a0*w.z; acc[0][3] += a0*w.w;
            acc[1][0] += a1*w.x; acc[1][1] += a1*w.y; acc[1][2] += a1*w.z; acc[1][3] += a1*w.w;
            acc[2][0] += a2*w.x; acc[2][1] += a2*w.y; acc[2][2] += a2*w.z; acc[2][3] += a2*w.w;
            acc[3][0] += a3*w.x; acc[3][1] += a3*w.y; acc[3][2] += a3*w.z; acc[3][3] += a3*w.w;
        }
        __syncthreads();
    }
    int b = bk >> 5;
    float4 bias = *(const float4*)(g_biasv + bk*COUTT + tx*4);
#pragma unroll
    for (int i = 0; i < 4; i++) {
        int gp = sgp[ty*4 + i];
        if (gp < 0) continue;
        int p = gp & 4095;
        size_t ob = (size_t)(b*COUTT + tx*4) * PP + p;
        out[ob          ] = acc[i][0] + bias.x;
        out[ob +   PP   ] = acc[i][1] + bias.y;
        out[ob + 2*PP   ] = acc[i][2] + bias.z;
        out[ob + 3*PP   ] = acc[i][3] + bias.w;
    }
}

// ---------------- launch ----------------
extern "C" void kernel_launch(void* const* d_in, const int* in_sizes, int n_in,
                              void* d_out, int out_size) {
    const float* x    = (const float*)d_in[0];
    const float* base = (const float*)d_in[1];
    const float* kw1 = (const float*)d_in[2];  const float* kb1 = (const float*)d_in[3];
    const float* kw2 = (const float*)d_in[4];  const float* kb2 = (const float*)d_in[5];
    const float* kw3 = (const float*)d_in[6];  const float* kb3 = (const float*)d_in[7];
    const float* bw1 = (const float*)d_in[8];  const float* bb1 = (const float*)d_in[9];
    const float* bw2 = (const float*)d_in[10]; const float* bb2 = (const float*)d_in[11];
    const float* bw3 = (const float*)d_in[12]; const float* bb3 = (const float*)d_in[13];
    float* out = (float*)d_out;

    // JAX key chain (partitionable/fold-like split): key(42) = (0,42)
    uint32_t bk0x, bk0y, bk1x, bk1y;
    threefry2x32(0u, 42u, 0u, 0u, bk0x, bk0y);   // batch 0 key
    threefry2x32(0u, 42u, 0u, 1u, bk1x, bk1y);   // batch 1 key
    uint4 s0, s1;
    {
        uint32_t c0, c1, u, v;
        threefry2x32(bk0x, bk0y, 0u, 1u, u, v); s0.x = u; s0.y = v;
        threefry2x32(bk0x, bk0y, 0u, 0u, c0, c1);
        threefry2x32(c0, c1, 0u, 1u, u, v);     s0.z = u; s0.w = v;
        threefry2x32(bk1x, bk1y, 0u, 1u, u, v); s1.x = u; s1.y = v;
        threefry2x32(bk1x, bk1y, 0u, 0u, c0, c1);
        threefry2x32(c0, c1, 0u, 1u, u, v);     s1.z = u; s1.w = v;
    }

    float* idx_out = (out_size >= BB*COUTT*PP + BB*PP) ? (out + BB*COUTT*PP) : nullptr;

    k_prep<<<2048, 128>>>(x);
    k_rankb<<<4, 1024>>>(s0, s1);
    k_seed<<<2, 1024>>>();
    k_kmeans<<<NBLK, 128>>>(idx_out, kw1, kb1, kw2, kb2, kw3, kb3,
                            bw1, bb1, bw2, bb2, bw3, bb3);
    k_wk<<<144, 512>>>(base);
    k_convg<<<MAXTILES, 256>>>(out);
}

// round 13
// speedup vs baseline: 1.1547x; 1.0185x over previous
#include <cuda_runtime.h>
#include <stdint.h>

#define BB 2
#define CC 32
#define HH 64
#define WW 64
#define PP 4096
#define FF 288
#define KK 32
#define NBB 32
#define HIDD 64
#define COUTT 64
#define NBLK 128      // persistent kmeans grid (64 blocks per batch)
#define MAXTILES 256
#define NSLOTS 48

// ---------------- device scratch (static, no allocation) ----------------
__device__ float    g_patches[BB*PP*FF];   // 9.4 MB
__device__ float    g_obs[BB*PP*CC];       // 1.0 MB
__device__ uint32_t g_rank[BB*2*PP];
__device__ int      g_permA[BB*PP];
__device__ int      g_initidx[BB*KK];
__device__ float    g_centers[BB*KK*CC];
__device__ float    g_part[NBLK][KK*CC + KK];   // per-block partials (no atomics)
__device__ float    g_shiftv[BB*KK];
__device__ int      g_cnt[BB*KK];
__device__ int      g_cursor[BB*KK];
__device__ int      g_off[BB*KK + 1];
__device__ int      g_plist[BB*PP];
__device__ int      g_tileBK[MAXTILES];
__device__ int      g_tileM0[MAXTILES];
__device__ int      g_ntiles;
__device__ float    g_attn[BB*KK*NBB];
__device__ float    g_biasv[BB*KK*COUTT];
__device__ float    g_wk[BB*KK*FF*COUTT];  // 4.7 MB
__device__ int      g_bslot[BB][NSLOTS];   // per-batch phase counters
__device__ int      g_gslot[4];            // global phase counters

// ---------------- Threefry-2x32 (JAX-compatible core) ----------------
__host__ __device__ inline void threefry2x32(uint32_t k0, uint32_t k1,
                                             uint32_t x0, uint32_t x1,
                                             uint32_t &o0, uint32_t &o1) {
    uint32_t ks2 = k0 ^ k1 ^ 0x1BD11BDAu;
    uint32_t v0 = x0 + k0, v1 = x1 + k1;
#define TF_R(r) { v0 += v1; v1 = (v1 << (r)) | (v1 >> (32 - (r))); v1 ^= v0; }
    TF_R(13) TF_R(15) TF_R(26) TF_R(6)   v0 += k1;  v1 += ks2 + 1u;
    TF_R(17) TF_R(29) TF_R(16) TF_R(24)  v0 += ks2; v1 += k0  + 2u;
    TF_R(13) TF_R(15) TF_R(26) TF_R(6)   v0 += k0;  v1 += k1  + 3u;
    TF_R(17) TF_R(29) TF_R(16) TF_R(24)  v0 += k1;  v1 += ks2 + 4u;
    TF_R(13) TF_R(15) TF_R(26) TF_R(6)   v0 += ks2; v1 += k0  + 5u;
#undef TF_R
    o0 = v0; o1 = v1;
}

// -------- barrier primitives: release-increment / acquire-poll ------------
__device__ __forceinline__ void bar_arrive(int* slot) {
    __syncthreads();
    if (threadIdx.x == 0) {
        asm volatile("red.release.gpu.global.add.s32 [%0], 1;"
                     :: "l"(slot) : "memory");
    }
}
__device__ __forceinline__ void bar_spin(int* slot, int target) {
    if (threadIdx.x == 0) {
        int v;
        do {
            asm volatile("ld.acquire.gpu.global.s32 %0, [%1];"
                         : "=r"(v) : "l"(slot) : "memory");
        } while (v < target);
    }
    __syncthreads();
}

// ---------------- unfold3 + channel-mean features (coalesced stores) ------
__global__ void k_prep(const float* __restrict__ x) {
    __shared__ float sbuf[4*FF];
    int warp = threadIdx.x >> 5, lane = threadIdx.x & 31;
    int gp = blockIdx.x * 4 + warp;           // 0..8191 = b*4096+p
    int b = gp >> 12, p = gp & 4095;
    int py = p >> 6, px = p & 63;
    const float* xc = x + (size_t)(b*CC + lane) * HH * WW;
    float* prow = sbuf + warp*FF + lane*9;
    float s = 0.f;
#pragma unroll
    for (int i = 0; i < 3; i++) {
        int yy = py + i - 1;
#pragma unroll
        for (int j = 0; j < 3; j++) {
            int xx = px + j - 1;
            float v = (yy >= 0 && yy < HH && xx >= 0 && xx < WW) ? xc[yy*WW + xx] : 0.f;
            prow[i*3 + j] = v;
            s += v;
        }
    }
    g_obs[(size_t)gp * CC + lane] = s / 9.f;
    __syncthreads();
    size_t base = (size_t)(blockIdx.x*4) * FF;
    for (int i = threadIdx.x; i < 4*FF; i += 128) g_patches[base + i] = sbuf[i];
}

// ---------------- bucket-based stable rank, keys fused in ------------------
__global__ void k_rankb(uint4 s0, uint4 s1) {
    int br = blockIdx.x;                 // 0..3 = b*2+r
    int b = br >> 1, r = br & 1;
    uint4 sk4 = b ? s1 : s0;
    uint32_t kk0 = r ? sk4.z : sk4.x;
    uint32_t kk1 = r ? sk4.w : sk4.y;
    __shared__ unsigned long long sorted[PP];   // 32 KB
    __shared__ int prefix[1025];
    __shared__ int cursor[1024];
    __shared__ int cnt[1024];
    __shared__ int wsum[32];
    int t = threadIdx.x;                 // 1024
    uint32_t kq[4];
#pragma unroll
    for (int q = 0; q < 4; q++) {
        uint32_t o0, o1;
        threefry2x32(kk0, kk1, 0u, (uint32_t)(t + q*1024), o0, o1);
        kq[q] = o0 ^ o1;
    }
    cnt[t] = 0;
    __syncthreads();
#pragma unroll
    for (int q = 0; q < 4; q++) atomicAdd(&cnt[kq[q] >> 22], 1);
    __syncthreads();
    int v = cnt[t];
    int lane = t & 31, wid = t >> 5;
    int s = v;
#pragma unroll
    for (int o = 1; o < 32; o <<= 1) { int u = __shfl_up_sync(0xffffffffu, s, o); if (lane >= o) s += u; }
    if (lane == 31) wsum[wid] = s;
    __syncthreads();
    if (wid == 0) {
        int ws = wsum[lane];
#pragma unroll
        for (int o = 1; o < 32; o <<= 1) { int u = __shfl_up_sync(0xffffffffu, ws, o); if (lane >= o) ws += u; }
        wsum[lane] = ws;
    }
    __syncthreads();
    int incl = s + (wid > 0 ? wsum[wid-1] : 0);
    prefix[t+1] = incl;
    if (t == 0) prefix[0] = 0;
    cursor[t] = incl - v;
    __syncthreads();
#pragma unroll
    for (int q = 0; q < 4; q++) {
        int p = atomicAdd(&cursor[kq[q] >> 22], 1);
        sorted[p] = ((unsigned long long)kq[q] << 32) | (uint32_t)(t + q*1024);
    }
    __syncthreads();
#pragma unroll
    for (int q = 0; q < 4; q++) {
        uint32_t key = kq[q];
        int i = t + q*1024;
        int bkt = key >> 22;
        int lo = prefix[bkt], hi = prefix[bkt+1];
        unsigned long long mine = ((unsigned long long)key << 32) | (uint32_t)i;
        int rr = lo;
        for (int j = lo; j < hi; j++) rr += (sorted[j] < mine) ? 1 : 0;
        g_rank[br*PP + i] = (uint32_t)rr;
    }
}

// ------- seed: global init + perm scatter + init-center gather (2 blocks) ---
__global__ void k_seed() {
    int b = blockIdx.x, t = threadIdx.x;   // 2 x 1024
    if (t < NSLOTS) g_bslot[b][t] = 0;
    if (b == 0 && t < 4) g_gslot[t] = 0;
    if (t < KK) { g_cnt[b*KK + t] = 0; g_cursor[b*KK + t] = 0; }
#pragma unroll
    for (int q = 0; q < 4; q++) {
        int i = t + q*1024;
        g_permA[b*PP + g_rank[(b*2)*PP + i]] = i;
    }
    __syncthreads();
#pragma unroll
    for (int q = 0; q < 4; q++) {
        int i = t + q*1024;
        uint32_t r1 = g_rank[(b*2+1)*PP + i];
        if (r1 < KK) g_initidx[b*KK + r1] = g_permA[b*PP + i];
    }
    __syncthreads();
    if (t < KK*CC) {
        int k = t >> 5, d = t & 31;
        g_centers[b*KK*CC + t] = g_obs[(size_t)(b*PP + g_initidx[b*KK + k])*CC + d];
    }
}

// --- persistent k-means + final assign + segmentation + sumsF + MLPs -------
__global__ void __launch_bounds__(128, 1) k_kmeans(
    float* idx_out,
    const float* __restrict__ kw1, const float* __restrict__ kb1,
    const float* __restrict__ kw2, const float* __restrict__ kb2,
    const float* __restrict__ kw3, const float* __restrict__ kb3,
    const float* __restrict__ bw1, const float* __restrict__ bb1,
    const float* __restrict__ bw2, const float* __restrict__ bb2,
    const float* __restrict__ bw3, const float* __restrict__ bb3)
{
    int bid = blockIdx.x;
    int b = bid >> 6;             // batch
    int sub = bid & 63;           // block within batch
    int t = threadIdx.x;          // 128
    int half = t & 1;
    int lp = t >> 1;              // local point 0..63
    int pi = sub*64 + lp;
    int lane = t & 31;
    int chunk = t >> 5;           // warp id 0..3
    int k0 = half * 16;
    __shared__ __align__(16) float sc[KK*CC];
    __shared__ __align__(16) float ssum4[4][KK*CC];   // per-warp-group partials
    __shared__ __align__(16) float sfeat[64*33];      // staged point features
    __shared__ int   slab[64];
    __shared__ float scn[KK];
    __shared__ float scnt[KK];
    __shared__ float sred[4][32];
    __shared__ float scred[64];
    __shared__ float s_sh;
    __shared__ int   soff[BB*KK + 1];

    // point features in registers (persist across all iterations)
    float s[CC]; float sn = 0.f;
    {
        const float* op = g_obs + (size_t)(b*PP + pi) * CC;
#pragma unroll
        for (int d = 0; d < CC; d++) { s[d] = op[d]; sn += s[d]*s[d]; }
    }
    // stage features to padded smem once (conflict-free)
#pragma unroll
    for (int i = 0; i < 16; i++) sfeat[lp*33 + k0 + i] = s[k0 + i];
    for (int i = t; i < KK*CC; i += 128) sc[i] = __ldcg(&g_centers[b*KK*CC + i]);
    __syncthreads();

    int ad = t & 31;              // accumulation dim
    int ag = t >> 5;              // accumulation group (warp)

    for (int it = 0; it < 20; it++) {
        int phase = it * 2;
        for (int i = t; i < 4*KK*CC; i += 128) ssum4[0][i] = 0.f;
        if (t < KK) {
            scnt[t] = 0.f;
            float q = 0.f;
#pragma unroll
            for (int d = 0; d < CC; d++) { float c = sc[t*CC + d]; q += c*c; }
            scn[t] = q;
        }
        __syncthreads();
        // ---- assign: 16 clusters per thread, pair-combined ----
        float best = 3.4028235e38f; int bi = 0;
        for (int k = k0; k < k0 + 16; k++) {
            float dot = 0.f;
#pragma unroll
            for (int d = 0; d < CC; d += 4) {
                float4 c4 = *(const float4*)&sc[k*CC + d];
                dot += s[d]*c4.x; dot += s[d+1]*c4.y;
                dot += s[d+2]*c4.z; dot += s[d+3]*c4.w;
            }
            float d2 = sn - 2.0f*dot + scn[k];
            if (d2 < best) { best = d2; bi = k; }
        }
        {
            float ob = __shfl_xor_sync(0xffffffffu, best, 1);
            int   ok = __shfl_xor_sync(0xffffffffu, bi, 1);
            if (ob < best || (ob == best && ok < bi)) { best = ob; bi = ok; }
        }
        // ---- counts via ballot + publish labels ----
#pragma unroll
        for (int k = 0; k < KK; k++) {
            unsigned m = __ballot_sync(0xffffffffu, bi == k);
            if (lane == k && m) atomicAdd(&scnt[k], (float)__popc(m) * 0.5f);
        }
        if (!half) slab[lp] = bi;
        __syncthreads();
        // ---- transposed accumulation: NO atomics, exclusive (g,d) columns --
        {
            float* acc = ssum4[ag];
            int p0 = ag * 16;
#pragma unroll
            for (int p = 0; p < 16; p++) {
                int lab = slab[p0 + p];
                float v = sfeat[(p0 + p)*33 + ad];
                acc[lab*CC + ad] += v;
            }
        }
        __syncthreads();
        // ---- flush combined partial (fixed group order, deterministic) ----
        for (int i = t; i < KK*CC; i += 128)
            __stcg(&g_part[bid][i],
                   ssum4[0][i] + ssum4[1][i] + ssum4[2][i] + ssum4[3][i]);
        if (t < KK) __stcg(&g_part[bid][KK*CC + t], scnt[t]);
        bar_arrive(&g_bslot[b][phase]);
        // ---- reducers (sub<32): wait for all 64 partials, 4-way chunked ----
        if (sub < KK) {
            bar_spin(&g_bslot[b][phase], 64);
            float acc = 0.f;
            {
                int e = sub*CC + lane;
#pragma unroll
                for (int j = 0; j < 16; j++)
                    acc += __ldcg(&g_part[b*64 + chunk*16 + j][e]);
            }
            sred[chunk][lane] = acc;
            float cacc = (t < 64) ? __ldcg(&g_part[b*64 + t][KK*CC + sub]) : 0.f;
            __syncthreads();
            if (t < 64) scred[t] = cacc;
            __syncthreads();
            if (t < 32) {
                float tot = sred[0][t] + sred[1][t] + sred[2][t] + sred[3][t];
                float c2 = scred[t] + scred[t + 32];
#pragma unroll
                for (int o = 16; o > 0; o >>= 1) c2 += __shfl_xor_sync(0xffffffffu, c2, o);
                float cv = c2;
                float oldc = sc[sub*CC + t];
                float nv = (cv > 0.f) ? (tot / fmaxf(cv, 1.f)) : oldc;
                float d = nv - oldc;
                float q = d*d;
#pragma unroll
                for (int o = 16; o > 0; o >>= 1) q += __shfl_xor_sync(0xffffffffu, q, o);
                __stcg(&g_centers[b*KK*CC + sub*CC + t], nv);
                if (t == 0) __stcg(&g_shiftv[b*KK + sub], sqrtf(q));
            }
            bar_arrive(&g_bslot[b][phase + 1]);
        }
        // ---- everyone: wait for 32 reducers, reload centers + shift ----
        bar_spin(&g_bslot[b][phase + 1], 32);
        for (int i = t; i < KK*CC; i += 128) sc[i] = __ldcg(&g_centers[b*KK*CC + i]);
        if (t < KK) {
            float sv = __ldcg(&g_shiftv[b*KK + t]);
#pragma unroll
            for (int o = 16; o > 0; o >>= 1) sv += __shfl_xor_sync(0xffffffffu, sv, o);
            if (t == 0) s_sh = sv;
        }
        __syncthreads();
        if ((it + 1) >= 20 || s_sh < 20.48f) break;   // TOL*n = 0.005*4096
    }

    // ---- final assignment with converged centers ----
    if (t < KK) {
        float q = 0.f;
#pragma unroll
        for (int d = 0; d < CC; d++) { float c = sc[t*CC + d]; q += c*c; }
        scn[t] = q;
    }
    __syncthreads();
    float best = 3.4028235e38f; int bi = 0;
    for (int k = k0; k < k0 + 16; k++) {
        float dot = 0.f;
#pragma unroll
        for (int d = 0; d < CC; d += 4) {
            float4 c4 = *(const float4*)&sc[k*CC + d];
            dot += s[d]*c4.x; dot += s[d+1]*c4.y;
            dot += s[d+2]*c4.z; dot += s[d+3]*c4.w;
        }
        float d2 = sn - 2.0f*dot + scn[k];
        if (d2 < best) { best = d2; bi = k; }
    }
    {
        float ob = __shfl_xor_sync(0xffffffffu, best, 1);
        int   ok = __shfl_xor_sync(0xffffffffu, bi, 1);
        if (ob < best || (ob == best && ok < bi)) { best = ob; bi = ok; }
    }
    if (!half) {
        if (idx_out) __stcg(&idx_out[b*PP + pi], (float)bi);
        atomicAdd(&g_cnt[b*KK + bi], 1);
    }
    bar_arrive(&g_gslot[0]);
    bar_spin(&g_gslot[0], NBLK);
    // ---- offsets: every block computes redundantly via smem scan ----
    {
        int c = 0, sc_ = 0;
        if (t < BB*KK) {
            c = __ldcg(&g_cnt[t]);
            sc_ = c;
#pragma unroll
            for (int o = 1; o < 32; o <<= 1) {
                int u = __shfl_up_sync(0xffffffffu, sc_, o);
                if (lane >= o) sc_ += u;
            }
        }
        __shared__ int w0tot;
        if (t == 31) w0tot = sc_;
        __syncthreads();
        if (t >= 32 && t < 64) sc_ += w0tot;
        if (t < BB*KK) soff[t + 1] = sc_;
        if (t == 0) soff[0] = 0;
        __syncthreads();
    }
    // block 0 publishes g_off + tile list (needed by k_convg)
    if (bid == 0) {
        if (t <= BB*KK) g_off[t] = soff[t];
        if (t == 0) {
            int nt = 0;
            for (int bk = 0; bk < BB*KK; bk++) {
                int c = soff[bk+1] - soff[bk];
                for (int m = 0; m < c; m += 64) { g_tileBK[nt] = bk; g_tileM0[nt] = m; nt++; }
            }
            g_ntiles = nt;
        }
    }
    // ---- scatter pixel list ----
    if (!half) {
        int bk = b*KK + bi;
        int pos = soff[bk] + atomicAdd(&g_cursor[bk], 1);
        __stcg(&g_plist[pos], b*PP + pi);
    }
    bar_arrive(&g_gslot[1]);
    bar_spin(&g_gslot[1], NBLK);
    // ---- per-cluster 288-dim partial sums: 2 blocks per cluster ----
    {
        int bk = bid & 63, h = bid >> 6;
        int lo = soff[bk], hi = soff[bk+1];
        float a0 = 0.f, a1 = 0.f, a2 = 0.f;
        for (int m = lo + h; m < hi; m += 2) {
            int gp = __ldcg(&g_plist[m]);
            const float* pr = g_patches + (size_t)gp*FF;
            a0 += __ldcg(&pr[t]); a1 += __ldcg(&pr[t+128]);
            if (t < 32) a2 += __ldcg(&pr[t+256]);
        }
        __stcg(&g_part[bid][t], a0);
        __stcg(&g_part[bid][t+128], a1);
        if (t < 32) __stcg(&g_part[bid][t+256], a2);
    }
    bar_arrive(&g_gslot[2]);
    if (bid >= BB*KK) return;
    bar_spin(&g_gslot[2], NBLK);
    // ---- combine + the two tiny MLPs + softmax (blocks 0..63) ----
    {
        int bk = bid;
        __shared__ float cen[FF];
        __shared__ float h1[HIDD];
        __shared__ float h2[HIDD];
        float dv = fmaxf((float)(soff[bk+1] - soff[bk]), 1.f);
        cen[t]     = (__ldcg(&g_part[bk][t])     + __ldcg(&g_part[bk+64][t]))     / dv;
        cen[t+128] = (__ldcg(&g_part[bk][t+128]) + __ldcg(&g_part[bk+64][t+128])) / dv;
        if (t < 32)
            cen[t+256] = (__ldcg(&g_part[bk][t+256]) + __ldcg(&g_part[bk+64][t+256])) / dv;
        __syncthreads();
        if (t < HIDD) {
            float a = kb1[t];
            for (int f = 0; f < FF; f++) a += cen[f]*kw1[f*HIDD + t];
            h1[t] = fmaxf(a, 0.f);
        }
        __syncthreads();
        if (t < HIDD) {
            float a = kb2[t];
#pragma unroll
            for (int i = 0; i < HIDD; i++) a += h1[i]*kw2[i*HIDD + t];
            h2[t] = fmaxf(a, 0.f);
        }
        __syncthreads();
        if (t < NBB) {
            float a = kb3[t];
#pragma unroll
            for (int i = 0; i < HIDD; i++) a += h2[i]*kw3[i*NBB + t];
            float m = a;
#pragma unroll
            for (int off = 16; off > 0; off >>= 1) m = fmaxf(m, __shfl_xor_sync(0xffffffffu, m, off));
            float e = expf(a - m);
            float ss = e;
#pragma unroll
            for (int off = 16; off > 0; off >>= 1) ss += __shfl_xor_sync(0xffffffffu, ss, off);
            g_attn[bk*NBB + t] = e / ss;
        }
        __syncthreads();
        if (t < HIDD) {
            float a = bb1[t];
            for (int f = 0; f < FF; f++) a += cen[f]*bw1[f*HIDD + t];
            h1[t] = fmaxf(a, 0.f);
        }
        __syncthreads();
        if (t < HIDD) {
            float a = bb2[t];
#pragma unroll
            for (int i = 0; i < HIDD; i++) a += h1[i]*bw2[i*HIDD + t];
            h2[t] = fmaxf(a, 0.f);
        }
        __syncthreads();
        if (t < COUTT) {
            float a = bb3[t];
#pragma unroll
            for (int i = 0; i < HIDD; i++) a += h2[i]*bw3[i*COUTT + t];
            g_biasv[bk*COUTT + t] = a;
        }
    }
}

// ---------------- kernels = attn @ base_kernels (row-split, 512 thr) -------
__global__ void k_wk(const float* __restrict__ base) {
    int col0 = blockIdx.x * 128;
    int t = threadIdx.x;             // 512
    int tc = t & 127;                // column within group
    int tr = t >> 7;                 // row group 0..3 (16 rows each)
    __shared__ float bt[NBB*128];
    __shared__ float at[BB*KK*NBB];
    for (int i = t; i < NBB*128; i += 512)
        bt[i] = base[(size_t)(i >> 7)*(FF*COUTT) + col0 + (i & 127)];
    for (int i = t; i < BB*KK*NBB; i += 512) at[i] = g_attn[i];
    __syncthreads();
#pragma unroll
    for (int rr = 0; rr < 16; rr++) {
        int row = tr*16 + rr;
        float acc = 0.f;
#pragma unroll
        for (int n = 0; n < NBB; n++) acc += at[row*NBB + n]*bt[n*128 + tc];
        g_wk[(size_t)row*(FF*COUTT) + col0 + tc] = acc;
    }
}

// ---------------- cluster-grouped GEMM conv ----------------
__global__ void k_convg(float* __restrict__ out) {
    __shared__ float As[64*36];
    __shared__ float Ws[32*64];
    __shared__ int sgp[64];
    int bid = blockIdx.x;
    if (bid >= g_ntiles) return;
    int bk = g_tileBK[bid], m0 = g_tileM0[bid];
    int lo = g_off[bk];
    int rows = g_off[bk+1] - lo - m0;
    if (rows > 64) rows = 64;
    int t = threadIdx.x;             // 256
    if (t < 64) sgp[t] = (t < rows) ? g_plist[lo + m0 + t] : -1;
    __syncthreads();
    int tx = t & 15, ty = t >> 4;
    float acc[4][4];
#pragma unroll
    for (int i = 0; i < 4; i++)
#pragma unroll
        for (int j = 0; j < 4; j++) acc[i][j] = 0.f;
    const float* wkbase = g_wk + (size_t)bk * (FF*COUTT);
    for (int kc = 0; kc < FF; kc += 32) {
#pragma unroll
        for (int u = 0; u < 2; u++) {
            int idx = t + u*256;
            int r = idx >> 3, c4 = idx & 7;
            int gp = sgp[r];
            float4 v = make_float4(0.f, 0.f, 0.f, 0.f);
            if (gp >= 0) v = *(const float4*)(g_patches + (size_t)gp*FF + kc + c4*4);
            *(float4*)(As + r*36 + c4*4) = v;
        }
#pragma unroll
        for (int u = 0; u < 2; u++) {
            int idx = t + u*256;
            int j = idx >> 4, c4 = idx & 15;
            *(float4*)(Ws + j*64 + c4*4) = *(const float4*)(wkbase + (size_t)(kc + j)*COUTT + c4*4);
        }
        __syncthreads();
#pragma unroll
        for (int j = 0; j < 32; j++) {
            float a0 = As[(ty*4+0)*36 + j];
            float a1 = As[(ty*4+1)*36 + j];
            float a2 = As[(ty*4+2)*36 + j];
            float a3 = As[(ty*4+3)*36 + j];
            float4 w = *(const float4*)(Ws + j*64 + tx*4);
            acc[0][0] += a0*w.x; acc[0][1] += a0*w.y; acc[0][2] += a0*w.z; acc[0][3] += a0*w.w;
            acc[1][0] += a1*w.x; acc[1][1] += a1*w.y; acc[1][2] += a1*w.z; acc[1][3] += a1*w.w;
            acc[2][0] += a2*w.x; acc[2][1] += a2*w.y; acc[2][2] += a2*w.z; acc[2][3] += a2*w.w;
            acc[3][0] += a3*w.x; acc[3][1] += a3*w.y; acc[3][2] += a3*w.z; acc[3][3] += a3*w.w;
        }
        __syncthreads();
    }
    int b = bk >> 5;
    float4 bias = *(const float4*)(g_biasv + bk*COUTT + tx*4);
#pragma unroll
    for (int i = 0; i < 4; i++) {
        int gp = sgp[ty*4 + i];
        if (gp < 0) continue;
        int p = gp & 4095;
        size_t ob = (size_t)(b*COUTT + tx*4) * PP + p;
        out[ob          ] = acc[i][0] + bias.x;
        out[ob +   PP   ] = acc[i][1] + bias.y;
        out[ob + 2*PP   ] = acc[i][2] + bias.z;
        out[ob + 3*PP   ] = acc[i][3] + bias.w;
    }
}

// ---------------- launch ----------------
extern "C" void kernel_launch(void* const* d_in, const int* in_sizes, int n_in,
                              void* d_out, int out_size) {
    const float* x    = (const float*)d_in[0];
    const float* base = (const float*)d_in[1];
    const float* kw1 = (const float*)d_in[2];  const float* kb1 = (const float*)d_in[3];
    const float* kw2 = (const float*)d_in[4];  const float* kb2 = (const float*)d_in[5];
    const float* kw3 = (const float*)d_in[6];  const float* kb3 = (const float*)d_in[7];
    const float* bw1 = (const float*)d_in[8];  const float* bb1 = (const float*)d_in[9];
    const float* bw2 = (const float*)d_in[10]; const float* bb2 = (const float*)d_in[11];
    const float* bw3 = (const float*)d_in[12]; const float* bb3 = (const float*)d_in[13];
    float* out = (float*)d_out;

    // JAX key chain (partitionable/fold-like split): key(42) = (0,42)
    uint32_t bk0x, bk0y, bk1x, bk1y;
    threefry2x32(0u, 42u, 0u, 0u, bk0x, bk0y);   // batch 0 key
    threefry2x32(0u, 42u, 0u, 1u, bk1x, bk1y);   // batch 1 key
    uint4 s0, s1;
    {
        uint32_t c0, c1, u, v;
        threefry2x32(bk0x, bk0y, 0u, 1u, u, v); s0.x = u; s0.y = v;
        threefry2x32(bk0x, bk0y, 0u, 0u, c0, c1);
        threefry2x32(c0, c1, 0u, 1u, u, v);     s0.z = u; s0.w = v;
        threefry2x32(bk1x, bk1y, 0u, 1u, u, v); s1.x = u; s1.y = v;
        threefry2x32(bk1x, bk1y, 0u, 0u, c0, c1);
        threefry2x32(c0, c1, 0u, 1u, u, v);     s1.z = u; s1.w = v;
    }

    float* idx_out = (out_size >= BB*COUTT*PP + BB*PP) ? (out + BB*COUTT*PP) : nullptr;

    k_prep<<<2048, 128>>>(x);
    k_rankb<<<4, 1024>>>(s0, s1);
    k_seed<<<2, 1024>>>();
    k_kmeans<<<NBLK, 128>>>(idx_out, kw1, kb1, kw2, kb2, kw3, kb3,
                            bw1, bb1, bw2, bb2, bw3, bb3);
    k_wk<<<144, 512>>>(base);
    k_convg<<<MAXTILES, 256>>>(out);
}